// round 8
// baseline (speedup 1.0000x reference)
#include <cuda_runtime.h>
#include <cuda_bf16.h>
#include <math.h>
#include <stdint.h>

// ---------------- problem constants ----------------
#define BB     4
#define TT     2048
#define DD     2048
#define HH     8
#define DK     128
#define DV     256
#define CHUNK  128
#define NCH    16
#define MROWS  (BB*TT)      // 8192
#define DHALF  (DD/2)       // 1024
#define SCALING 0.0625f
#define INV_NORM_GK (1.0f/16.0f)
#define NCHUNKS (BB*NCH*HH) // 512
#define NBLOBS  (BB*HH*4*NCH) // 2048 state blobs
#define WTROWS 8192         // combined transposed weights: Q|K|V|G|O

// ---------------- scratch ----------------
__device__ float g_QK [(size_t)MROWS * 2048];
__device__ float g_GK [(size_t)MROWS * DHALF];
__device__ float g_KG1[(size_t)MROWS * 16];
__device__ float g_DEC[(size_t)BB * NCH * DHALF];
__device__ float g_G  [(size_t)MROWS * DD];
__device__ float g_O  [(size_t)MROWS * DD];
__device__ __nv_bfloat16 g_XH [(size_t)MROWS * DD];
__device__ __nv_bfloat16 g_XL [(size_t)MROWS * DD];
__device__ __nv_bfloat16 g_WTH[(size_t)WTROWS * DD];
__device__ __nv_bfloat16 g_WTL[(size_t)WTROWS * DD];
__device__ __nv_bfloat16 g_PH [(size_t)MROWS * DD];
__device__ __nv_bfloat16 g_PL [(size_t)MROWS * DD];
__device__ __nv_bfloat16 g_QH [(size_t)MROWS * DHALF];
__device__ __nv_bfloat16 g_QL [(size_t)MROWS * DHALF];
__device__ __nv_bfloat16 g_KH [(size_t)MROWS * DHALF];
__device__ __nv_bfloat16 g_KL [(size_t)MROWS * DHALF];
__device__ __nv_bfloat16 g_KDH[(size_t)MROWS * DHALF];
__device__ __nv_bfloat16 g_KDL[(size_t)MROWS * DHALF];
__device__ __nv_bfloat16 g_VH [(size_t)MROWS * DD];
__device__ __nv_bfloat16 g_VL [(size_t)MROWS * DD];
__device__ __nv_bfloat16 g_AH [(size_t)NCHUNKS * CHUNK * CHUNK];
__device__ __nv_bfloat16 g_AL [(size_t)NCHUNKS * CHUNK * CHUNK];
__device__ __nv_bfloat16 g_SBH[(size_t)NBLOBS * 64 * 128];
__device__ __nv_bfloat16 g_SBL[(size_t)NBLOBS * 64 * 128];

// ================= helpers =================
__device__ __forceinline__ uint32_t smem_u32(const void* p) {
    uint32_t a;
    asm("{ .reg .u64 t; cvta.to.shared.u64 t, %1; cvt.u32.u64 %0, t; }" : "=r"(a) : "l"(p));
    return a;
}
__device__ __forceinline__ void cpasync16(uint32_t dst, const void* src) {
    asm volatile("cp.async.cg.shared.global [%0], [%1], 16;" :: "r"(dst), "l"(src) : "memory");
}
__device__ __forceinline__ void ldsm_x4(uint32_t* r, uint32_t addr) {
    asm volatile("ldmatrix.sync.aligned.m8n8.x4.shared.b16 {%0,%1,%2,%3}, [%4];"
                 : "=r"(r[0]), "=r"(r[1]), "=r"(r[2]), "=r"(r[3]) : "r"(addr));
}
__device__ __forceinline__ void mma16816(float* c, const uint32_t* a, const uint32_t* b) {
    asm volatile(
        "mma.sync.aligned.m16n8k16.row.col.f32.bf16.bf16.f32 "
        "{%0,%1,%2,%3}, {%4,%5,%6,%7}, {%8,%9}, {%0,%1,%2,%3};"
        : "+f"(c[0]), "+f"(c[1]), "+f"(c[2]), "+f"(c[3])
        : "r"(a[0]), "r"(a[1]), "r"(a[2]), "r"(a[3]), "r"(b[0]), "r"(b[1]));
}
static __device__ __forceinline__ uint32_t sw128(uint32_t o) { return o ^ ((o >> 3) & 0x70); }

// acc[MF][4][4] += A_tile @ B_tile^T over K=128 (2 sw128 K-subtiles)
template<int MF>
__device__ __forceinline__ void mma_combo(float (*acc)[4][4], uint32_t Ab, uint32_t abs_,
                                          uint32_t Bb, uint32_t bbs, int mw, int nw, int lane)
{
#pragma unroll
    for (int kb = 0; kb < 2; kb++) {
#pragma unroll
        for (int ks = 0; ks < 4; ks++) {
            uint32_t af[MF][4];
#pragma unroll
            for (int mf = 0; mf < MF; mf++) {
                int row = mw + mf * 16 + (lane & 15);
                uint32_t bo = (uint32_t)(row << 7) + (uint32_t)(ks << 5) + ((lane >> 4) << 4);
                ldsm_x4(af[mf], Ab + kb * abs_ + sw128(bo));
            }
            uint32_t bfr[4][2];
#pragma unroll
            for (int half = 0; half < 2; half++) {
                int i2 = lane >> 3;
                int row = nw + half * 16 + ((i2 >> 1) << 3) + (lane & 7);
                uint32_t bo = (uint32_t)(row << 7) + (uint32_t)(ks << 5) + ((i2 & 1) << 4);
                uint32_t r[4];
                ldsm_x4(r, Bb + kb * bbs + sw128(bo));
                bfr[half * 2][0] = r[0];     bfr[half * 2][1] = r[1];
                bfr[half * 2 + 1][0] = r[2]; bfr[half * 2 + 1][1] = r[3];
            }
#pragma unroll
            for (int mf = 0; mf < MF; mf++)
#pragma unroll
                for (int nf = 0; nf < 4; nf++)
                    mma16816(acc[mf][nf], af[mf], bfr[nf]);
        }
    }
}

// ======================================================================
// gemm3: shared-fragment bf16x3 GEMM, 3-stage cp.async pipeline,
// 512 threads (16 warps, 32x32 warp tiles), ONE __syncthreads per chunk.
// Epilogue regions: cols < nsplit -> bf16 split (SHo/SLo, row stride nsplit);
// cols >= nsplit -> fp32 C (+bias), row stride N-nsplit.
// ======================================================================
__global__ __launch_bounds__(512, 1)
void gemm3(const __nv_bfloat16* __restrict__ AHp, const __nv_bfloat16* __restrict__ ALp,
           const __nv_bfloat16* __restrict__ BHp, const __nv_bfloat16* __restrict__ BLp,
           float* __restrict__ C, __nv_bfloat16* __restrict__ SHo, __nv_bfloat16* __restrict__ SLo,
           int M, int N, int K, int nsplit, float alpha, const float* __restrict__ bias)
{
    extern __shared__ char smem[];
    const uint32_t sbase = smem_u32(smem);
    const int tid = threadIdx.x;
    const int wid = tid >> 5, lane = tid & 31;
    const int m0 = blockIdx.y * 128, n0 = blockIdx.x * 128;
    const int mw = (wid & 3) * 32, nw = (wid >> 2) * 32;
    const int TOT = K >> 6;

    float acc[2][4][4];
#pragma unroll
    for (int i = 0; i < 2; i++)
#pragma unroll
        for (int j = 0; j < 4; j++)
#pragma unroll
            for (int l = 0; l < 4; l++) acc[i][j][l] = 0.f;

    auto issue = [&](int it) {
        const int k0 = it << 6;
        const uint32_t st = sbase + (uint32_t)(it % 3) * 65536u;
#pragma unroll
        for (int l = 0; l < 2; l++) {
            int c = tid + (l << 9);
            int row = c >> 3;
            uint32_t dst = sw128((uint32_t)(row << 7) + ((c & 7) << 4));
            int el = (c & 7) << 3;
            size_t ao = (size_t)(m0 + row) * K + k0 + el;
            size_t bo = (size_t)(n0 + row) * K + k0 + el;
            cpasync16(st + dst,         AHp + ao);
            cpasync16(st + 16384 + dst, ALp + ao);
            cpasync16(st + 32768 + dst, BHp + bo);
            cpasync16(st + 49152 + dst, BLp + bo);
        }
        asm volatile("cp.async.commit_group;" ::: "memory");
    };

    issue(0);
    if (TOT > 1) issue(1);
    for (int it = 0; it < TOT; it++) {
        if (it + 1 < TOT) {
            asm volatile("cp.async.wait_group 1;" ::: "memory");
        } else {
            asm volatile("cp.async.wait_group 0;" ::: "memory");
        }
        __syncthreads();
        const uint32_t st = sbase + (uint32_t)(it % 3) * 65536u;
#pragma unroll
        for (int ks = 0; ks < 4; ks++) {
            uint32_t afH[2][4], afL[2][4], bfH[4][2], bfL[4][2];
#pragma unroll
            for (int mf = 0; mf < 2; mf++) {
                int row = mw + mf * 16 + (lane & 15);
                uint32_t bo = (uint32_t)(row << 7) + (uint32_t)(ks << 5) + ((lane >> 4) << 4);
                uint32_t so = sw128(bo);
                ldsm_x4(afH[mf], st + so);
                ldsm_x4(afL[mf], st + 16384 + so);
            }
#pragma unroll
            for (int half = 0; half < 2; half++) {
                int i2 = lane >> 3;
                int row = nw + half * 16 + ((i2 >> 1) << 3) + (lane & 7);
                uint32_t bo = (uint32_t)(row << 7) + (uint32_t)(ks << 5) + ((i2 & 1) << 4);
                uint32_t so = sw128(bo);
                uint32_t r[4];
                ldsm_x4(r, st + 32768 + so);
                bfH[half * 2][0] = r[0];     bfH[half * 2][1] = r[1];
                bfH[half * 2 + 1][0] = r[2]; bfH[half * 2 + 1][1] = r[3];
                ldsm_x4(r, st + 49152 + so);
                bfL[half * 2][0] = r[0];     bfL[half * 2][1] = r[1];
                bfL[half * 2 + 1][0] = r[2]; bfL[half * 2 + 1][1] = r[3];
            }
#pragma unroll
            for (int mf = 0; mf < 2; mf++)
#pragma unroll
                for (int nf = 0; nf < 4; nf++) {
                    mma16816(acc[mf][nf], afH[mf], bfH[nf]);
                    mma16816(acc[mf][nf], afH[mf], bfL[nf]);
                    mma16816(acc[mf][nf], afL[mf], bfH[nf]);
                }
        }
        if (it + 2 < TOT) issue(it + 2);
    }

    const int rb = m0 + mw + (lane >> 2);
    const int cb = n0 + nw + ((lane & 3) << 1);
    const bool split_region = (n0 < nsplit);
    const int cstride = N - nsplit;
#pragma unroll
    for (int mf = 0; mf < 2; mf++) {
#pragma unroll
        for (int half = 0; half < 2; half++) {
            int row = rb + mf * 16 + half * 8;
#pragma unroll
            for (int nf = 0; nf < 4; nf++) {
                int col = cb + nf * 8;
                float vx = alpha * acc[mf][nf][half * 2 + 0];
                float vy = alpha * acc[mf][nf][half * 2 + 1];
                if (split_region) {
                    __nv_bfloat16 h0 = __float2bfloat16(vx);
                    __nv_bfloat16 h1 = __float2bfloat16(vy);
                    __nv_bfloat16 l0 = __float2bfloat16(vx - __bfloat162float(h0));
                    __nv_bfloat16 l1 = __float2bfloat16(vy - __bfloat162float(h1));
                    *(__nv_bfloat162*)(SHo + (size_t)row * nsplit + col) = __nv_bfloat162(h0, h1);
                    *(__nv_bfloat162*)(SLo + (size_t)row * nsplit + col) = __nv_bfloat162(l0, l1);
                } else {
                    int cc = col - nsplit;
                    if (bias) { vx += bias[cc]; vy += bias[cc + 1]; }
                    float2 v; v.x = vx; v.y = vy;
                    *(float2*)(C + (size_t)row * cstride + cc) = v;
                }
            }
        }
    }
}

// ======================================================================
// A-chunk kernel (verified): A = qd @ kexp^T, tril, split to bf16.
// ======================================================================
__global__ __launch_bounds__(256, 1)
void akernel(const __nv_bfloat16* __restrict__ QH, const __nv_bfloat16* __restrict__ QL,
             const __nv_bfloat16* __restrict__ KH, const __nv_bfloat16* __restrict__ KL,
             __nv_bfloat16* __restrict__ AH, __nv_bfloat16* __restrict__ AL)
{
    extern __shared__ char smemc[];
    const uint32_t sb = smem_u32(smemc);
    const uint32_t oQH = 0, oQL = 32768, oKH = 65536, oKL = 98304;
    const int tid = threadIdx.x;
    const int wid = tid >> 5, lane = tid & 31;
    const int h = blockIdx.x, ch = blockIdx.y, bb = blockIdx.z;
    const int m0 = bb * TT + ch * CHUNK;
    const int colQ = h * 128;
    const size_t chA = (size_t)((bb * NCH + ch) * HH + h) * 16384;

#pragma unroll
    for (int l = 0; l < 8; l++) {
        int idx = tid + (l << 8);
        int row = idx >> 4, u = idx & 15;
        int kb = u >> 3, sub = u & 7;
        uint32_t dst = (uint32_t)kb * 16384u + sw128((uint32_t)(row << 7) + (sub << 4));
        size_t so = (size_t)(m0 + row) * DHALF + colQ + kb * 64 + sub * 8;
        cpasync16(sb + oQH + dst, QH + so);
        cpasync16(sb + oQL + dst, QL + so);
        cpasync16(sb + oKH + dst, KH + so);
        cpasync16(sb + oKL + dst, KL + so);
    }
    asm volatile("cp.async.commit_group;" ::: "memory");
    asm volatile("cp.async.wait_group 0;" ::: "memory");
    __syncthreads();

    const int mw = (wid & 1) * 64, nw = (wid >> 1) * 32;
    float acc[4][4][4];
#pragma unroll
    for (int i = 0; i < 4; i++)
#pragma unroll
        for (int j = 0; j < 4; j++)
#pragma unroll
            for (int l = 0; l < 4; l++) acc[i][j][l] = 0.f;

    mma_combo<4>(acc, sb + oQH, 16384, sb + oKH, 16384, mw, nw, lane);
    mma_combo<4>(acc, sb + oQH, 16384, sb + oKL, 16384, mw, nw, lane);
    mma_combo<4>(acc, sb + oQL, 16384, sb + oKH, 16384, mw, nw, lane);

#pragma unroll
    for (int mf = 0; mf < 4; mf++) {
#pragma unroll
        for (int half = 0; half < 2; half++) {
            int i = mw + mf * 16 + half * 8 + (lane >> 2);
#pragma unroll
            for (int nf = 0; nf < 4; nf++) {
                int j = nw + nf * 8 + ((lane & 3) << 1);
                float v0 = (j     <= i) ? acc[mf][nf][half * 2 + 0] : 0.f;
                float v1 = (j + 1 <= i) ? acc[mf][nf][half * 2 + 1] : 0.f;
                __nv_bfloat16 h0 = __float2bfloat16(v0);
                __nv_bfloat16 h1 = __float2bfloat16(v1);
                __nv_bfloat16 l0 = __float2bfloat16(v0 - __bfloat162float(h0));
                __nv_bfloat16 l1 = __float2bfloat16(v1 - __bfloat162float(h1));
                size_t oi = chA + (size_t)i * 128 + j;
                *(__nv_bfloat162*)(AH + oi) = __nv_bfloat162(h0, h1);
                *(__nv_bfloat162*)(AL + oi) = __nv_bfloat162(l0, l1);
            }
        }
    }
}

// ======================================================================
// state_kernel: serial S recurrence per (b,h,dv64) -> pre-update S^T blobs
// ======================================================================
__global__ __launch_bounds__(256, 1)
void state_kernel(const __nv_bfloat16* __restrict__ KDH, const __nv_bfloat16* __restrict__ KDL,
                  const __nv_bfloat16* __restrict__ VH, const __nv_bfloat16* __restrict__ VL,
                  const float* __restrict__ DEC,
                  __nv_bfloat16* __restrict__ SBH, __nv_bfloat16* __restrict__ SBL)
{
    extern __shared__ char smemc[];
    const uint32_t sb = smem_u32(smemc);
    const uint32_t oKT = 0, oKTl = 32768, oVH = 65536, oVL = 81920;
    const uint32_t oSC = 98304, oSCl = 114688, oS32 = 131072;
    float* ST32 = (float*)(smemc + oS32);           // [n=64][d=128]
    __shared__ float dec[128];

    const int tid = threadIdx.x;
    const int wid = tid >> 5, lane = tid & 31;
    const int vsl = blockIdx.x, h = blockIdx.y, bb = blockIdx.z;
    const int colQ = h * 128;
    const int colV = h * 256 + vsl * 64;
    const int mw = (wid & 3) * 32, nw = (wid >> 2) * 32;
    const int blobbase = ((bb * HH + h) * 4 + vsl) * NCH;

    for (int i = tid; i < 8192; i += 256) ST32[i] = 0.f;

    for (int ch = 0; ch < NCH; ch++) {
        const int m0 = bb * TT + ch * CHUNK;
        __syncthreads();

#pragma unroll
        for (int l = 0; l < 32; l++) {
            int idx = tid + (l << 8);
            int j = idx >> 6, d = (idx & 63) << 1;
            uint32_t wv = *(const uint32_t*)(KDH + (size_t)(m0 + j) * DHALF + colQ + d);
            uint32_t wl = *(const uint32_t*)(KDL + (size_t)(m0 + j) * DHALF + colQ + d);
            uint32_t kbo = (uint32_t)(j >> 6) * 16384u;
            uint32_t off0 = kbo + sw128((uint32_t)(d << 7) + ((j & 63) << 1));
            uint32_t off1 = kbo + sw128((uint32_t)((d + 1) << 7) + ((j & 63) << 1));
            *(unsigned short*)(smemc + oKT  + off0) = (unsigned short)(wv & 0xffff);
            *(unsigned short*)(smemc + oKT  + off1) = (unsigned short)(wv >> 16);
            *(unsigned short*)(smemc + oKTl + off0) = (unsigned short)(wl & 0xffff);
            *(unsigned short*)(smemc + oKTl + off1) = (unsigned short)(wl >> 16);
        }
#pragma unroll
        for (int l = 0; l < 16; l++) {
            int idx = tid + (l << 8);
            int j = idx >> 5, n = (idx & 31) << 1;
            uint32_t wv = *(const uint32_t*)(VH + (size_t)(m0 + j) * DD + colV + n);
            uint32_t wl = *(const uint32_t*)(VL + (size_t)(m0 + j) * DD + colV + n);
            uint32_t kbo = (uint32_t)(j >> 6) * 8192u;
            uint32_t off0 = kbo + sw128((uint32_t)(n << 7) + ((j & 63) << 1));
            uint32_t off1 = kbo + sw128((uint32_t)((n + 1) << 7) + ((j & 63) << 1));
            *(unsigned short*)(smemc + oVH + off0) = (unsigned short)(wv & 0xffff);
            *(unsigned short*)(smemc + oVH + off1) = (unsigned short)(wv >> 16);
            *(unsigned short*)(smemc + oVL + off0) = (unsigned short)(wl & 0xffff);
            *(unsigned short*)(smemc + oVL + off1) = (unsigned short)(wl >> 16);
        }
        for (int i = tid; i < 8192; i += 256) {
            int n = i >> 7, d = i & 127;
            float v = ST32[i];
            __nv_bfloat16 hv = __float2bfloat16(v);
            __nv_bfloat16 lv = __float2bfloat16(v - __bfloat162float(hv));
            uint32_t off = (uint32_t)(d >> 6) * 8192u + sw128((uint32_t)(n << 7) + ((d & 63) << 1));
            *(__nv_bfloat16*)(smemc + oSC  + off) = hv;
            *(__nv_bfloat16*)(smemc + oSCl + off) = lv;
        }
        if (tid < 128) dec[tid] = DEC[(size_t)(bb * NCH + ch) * DHALF + colQ + tid];
        __syncthreads();

        {
            const float4* sH = (const float4*)(smemc + oSC);
            const float4* sL = (const float4*)(smemc + oSCl);
            float4* dH = (float4*)(SBH + (size_t)(blobbase + ch) * 8192);
            float4* dL = (float4*)(SBL + (size_t)(blobbase + ch) * 8192);
            for (int i = tid; i < 1024; i += 256) { dH[i] = sH[i]; dL[i] = sL[i]; }
        }

        float sacc[2][4][4];
#pragma unroll
        for (int i = 0; i < 2; i++)
#pragma unroll
            for (int j = 0; j < 4; j++)
#pragma unroll
                for (int l = 0; l < 4; l++) sacc[i][j][l] = 0.f;

        mma_combo<2>(sacc, sb + oKT,  16384, sb + oVH, 8192, mw, nw, lane);
        mma_combo<2>(sacc, sb + oKT,  16384, sb + oVL, 8192, mw, nw, lane);
        mma_combo<2>(sacc, sb + oKTl, 16384, sb + oVH, 8192, mw, nw, lane);

#pragma unroll
        for (int mf = 0; mf < 2; mf++) {
#pragma unroll
            for (int half = 0; half < 2; half++) {
                int d = mw + mf * 16 + half * 8 + (lane >> 2);
                float dv = dec[d];
#pragma unroll
                for (int nf = 0; nf < 4; nf++) {
                    int n = nw + nf * 8 + ((lane & 3) << 1);
                    int i0 = n * 128 + d, i1 = (n + 1) * 128 + d;
                    ST32[i0] = dv * ST32[i0] + sacc[mf][nf][half * 2 + 0];
                    ST32[i1] = dv * ST32[i1] + sacc[mf][nf][half * 2 + 1];
                }
            }
        }
    }
}

// ======================================================================
// o_kernel: fully parallel O phase. block per (b,h,ch,dv64).
// ======================================================================
__global__ __launch_bounds__(256, 1)
void o_kernel(const __nv_bfloat16* __restrict__ QH, const __nv_bfloat16* __restrict__ QL,
              const __nv_bfloat16* __restrict__ AH, const __nv_bfloat16* __restrict__ AL,
              const __nv_bfloat16* __restrict__ VH, const __nv_bfloat16* __restrict__ VL,
              const __nv_bfloat16* __restrict__ SBH, const __nv_bfloat16* __restrict__ SBL,
              float* __restrict__ O)
{
    extern __shared__ char smemc[];
    const uint32_t sb = smem_u32(smemc);
    const uint32_t oQH = 0, oQL = 32768, oAH = 65536, oAL = 98304;
    const uint32_t oVH = 131072, oVL = 147456, oSH = 163840, oSL = 180224;

    const int tid = threadIdx.x;
    const int wid = tid >> 5, lane = tid & 31;
    const int ch = blockIdx.x >> 2, vsl = blockIdx.x & 3;
    const int h = blockIdx.y, bb = blockIdx.z;
    const int m0 = bb * TT + ch * CHUNK;
    const int colQ = h * 128;
    const int colV = h * 256 + vsl * 64;
    const size_t chA = (size_t)((bb * NCH + ch) * HH + h) * 16384;
    const size_t blob = (size_t)(((bb * HH + h) * 4 + vsl) * NCH + ch) * 8192;
    const int mw = (wid & 3) * 32, nw = (wid >> 2) * 32;

#pragma unroll
    for (int l = 0; l < 8; l++) {
        int idx = tid + (l << 8);
        int row = idx >> 4, u = idx & 15;
        int kb = u >> 3, sub = u & 7;
        uint32_t dst = (uint32_t)kb * 16384u + sw128((uint32_t)(row << 7) + (sub << 4));
        size_t so = (size_t)(m0 + row) * DHALF + colQ + kb * 64 + sub * 8;
        cpasync16(sb + oQH + dst, QH + so);
        cpasync16(sb + oQL + dst, QL + so);
        size_t sa = chA + (size_t)row * 128 + kb * 64 + sub * 8;
        cpasync16(sb + oAH + dst, AH + sa);
        cpasync16(sb + oAL + dst, AL + sa);
    }
#pragma unroll
    for (int l = 0; l < 4; l++) {
        int i = tid + (l << 8);
        cpasync16(sb + oSH + (i << 4), SBH + blob + (size_t)i * 8);
        cpasync16(sb + oSL + (i << 4), SBL + blob + (size_t)i * 8);
    }
    asm volatile("cp.async.commit_group;" ::: "memory");

#pragma unroll
    for (int l = 0; l < 16; l++) {
        int idx = tid + (l << 8);
        int j = idx >> 5, n = (idx & 31) << 1;
        uint32_t wv = *(const uint32_t*)(VH + (size_t)(m0 + j) * DD + colV + n);
        uint32_t wl = *(const uint32_t*)(VL + (size_t)(m0 + j) * DD + colV + n);
        uint32_t kbo = (uint32_t)(j >> 6) * 8192u;
        uint32_t off0 = kbo + sw128((uint32_t)(n << 7) + ((j & 63) << 1));
        uint32_t off1 = kbo + sw128((uint32_t)((n + 1) << 7) + ((j & 63) << 1));
        *(unsigned short*)(smemc + oVH + off0) = (unsigned short)(wv & 0xffff);
        *(unsigned short*)(smemc + oVH + off1) = (unsigned short)(wv >> 16);
        *(unsigned short*)(smemc + oVL + off0) = (unsigned short)(wl & 0xffff);
        *(unsigned short*)(smemc + oVL + off1) = (unsigned short)(wl >> 16);
    }
    asm volatile("cp.async.wait_group 0;" ::: "memory");
    __syncthreads();

    float acc[2][4][4];
#pragma unroll
    for (int i = 0; i < 2; i++)
#pragma unroll
        for (int j = 0; j < 4; j++)
#pragma unroll
            for (int l = 0; l < 4; l++) acc[i][j][l] = 0.f;

    mma_combo<2>(acc, sb + oAH, 16384, sb + oVH, 8192, mw, nw, lane);
    mma_combo<2>(acc, sb + oAH, 16384, sb + oVL, 8192, mw, nw, lane);
    mma_combo<2>(acc, sb + oAL, 16384, sb + oVH, 8192, mw, nw, lane);
    mma_combo<2>(acc, sb + oQH, 16384, sb + oSH, 8192, mw, nw, lane);
    mma_combo<2>(acc, sb + oQH, 16384, sb + oSL, 8192, mw, nw, lane);
    mma_combo<2>(acc, sb + oQL, 16384, sb + oSH, 8192, mw, nw, lane);

#pragma unroll
    for (int mf = 0; mf < 2; mf++) {
#pragma unroll
        for (int half = 0; half < 2; half++) {
            int row = m0 + mw + mf * 16 + half * 8 + (lane >> 2);
#pragma unroll
            for (int nf = 0; nf < 4; nf++) {
                int col = colV + nw + nf * 8 + ((lane & 3) << 1);
                float2 v;
                v.x = acc[mf][nf][half * 2 + 0];
                v.y = acc[mf][nf][half * 2 + 1];
                *(float2*)&O[(size_t)row * DD + col] = v;
            }
        }
    }
}

// ======================================================================
// split x -> bf16 hi/lo
// ======================================================================
__global__ void xsplit(const float4* __restrict__ X, __nv_bfloat16* __restrict__ H,
                       __nv_bfloat16* __restrict__ L, int n4)
{
    int i = blockIdx.x * blockDim.x + threadIdx.x;
    if (i >= n4) return;
    float4 v = X[i];
    __nv_bfloat16 h0 = __float2bfloat16(v.x), h1 = __float2bfloat16(v.y);
    __nv_bfloat16 h2 = __float2bfloat16(v.z), h3 = __float2bfloat16(v.w);
    __nv_bfloat16 l0 = __float2bfloat16(v.x - __bfloat162float(h0));
    __nv_bfloat16 l1 = __float2bfloat16(v.y - __bfloat162float(h1));
    __nv_bfloat16 l2 = __float2bfloat16(v.z - __bfloat162float(h2));
    __nv_bfloat16 l3 = __float2bfloat16(v.w - __bfloat162float(h3));
    __nv_bfloat162* Hp = (__nv_bfloat162*)H;
    __nv_bfloat162* Lp = (__nv_bfloat162*)L;
    Hp[i * 2]     = __nv_bfloat162(h0, h1);
    Hp[i * 2 + 1] = __nv_bfloat162(h2, h3);
    Lp[i * 2]     = __nv_bfloat162(l0, l1);
    Lp[i * 2 + 1] = __nv_bfloat162(l2, l3);
}

// ======================================================================
// transpose W [K,N] -> combined WT buffer rows [rowoff..rowoff+N), x alpha
// ======================================================================
__global__ void wsplit_t(const float* __restrict__ W, __nv_bfloat16* __restrict__ Th,
                         __nv_bfloat16* __restrict__ Tl, int K, int N, int rowoff, float alpha)
{
    __shared__ float t[32][33];
    const int n0 = blockIdx.x * 32, k0 = blockIdx.y * 32;
    const int tx = threadIdx.x, ty = threadIdx.y;
#pragma unroll
    for (int i = 0; i < 4; i++) {
        int k = ty + i * 8;
        t[k][tx] = W[(size_t)(k0 + k) * N + n0 + tx];
    }
    __syncthreads();
#pragma unroll
    for (int i = 0; i < 4; i++) {
        int n = ty + i * 8;
        float v = t[tx][n] * alpha;
        __nv_bfloat16 h = __float2bfloat16(v);
        size_t oi = (size_t)(rowoff + n0 + n) * K + k0 + tx;
        Th[oi] = h;
        Tl[oi] = __float2bfloat16(v - __bfloat162float(h));
    }
}

// ======================================================================
// kg1: out[M,16] = x @ Wkg1. warp per row.
// ======================================================================
__global__ void kg1_kernel(const float* __restrict__ x, const float* __restrict__ W1,
                           float* __restrict__ out)
{
    const int wid = threadIdx.x >> 5, lane = threadIdx.x & 31;
    const int row = blockIdx.x * 8 + wid;
    const float* xp = x + (size_t)row * DD;
    float acc[16];
#pragma unroll
    for (int c = 0; c < 16; c++) acc[c] = 0.f;
    for (int k = lane; k < DD; k += 32) {
        float xv = xp[k];
        const float4* wp = (const float4*)(W1 + (size_t)k * 16);
        float4 w0 = wp[0], w1 = wp[1], w2 = wp[2], w3 = wp[3];
        acc[0]  += xv * w0.x; acc[1]  += xv * w0.y; acc[2]  += xv * w0.z; acc[3]  += xv * w0.w;
        acc[4]  += xv * w1.x; acc[5]  += xv * w1.y; acc[6]  += xv * w1.z; acc[7]  += xv * w1.w;
        acc[8]  += xv * w2.x; acc[9]  += xv * w2.y; acc[10] += xv * w2.z; acc[11] += xv * w2.w;
        acc[12] += xv * w3.x; acc[13] += xv * w3.y; acc[14] += xv * w3.z; acc[15] += xv * w3.w;
    }
#pragma unroll
    for (int c = 0; c < 16; c++) {
        float v = acc[c];
#pragma unroll
        for (int off = 16; off; off >>= 1) v += __shfl_xor_sync(0xFFFFFFFFu, v, off);
        if (lane == 0) out[(size_t)row * 16 + c] = v;
    }
}

// ======================================================================
// gk = log_sigmoid(KG1 @ Wkg2 + bkg2) / 16   (fast intrinsics)
// ======================================================================
__global__ void gk_kernel(const float* __restrict__ KG1,
                          const float* __restrict__ W2,
                          const float* __restrict__ b2,
                          float* __restrict__ GK)
{
    __shared__ float a[16];
    int m = blockIdx.x;
    if (threadIdx.x < 16) a[threadIdx.x] = KG1[(size_t)m * 16 + threadIdx.x];
    __syncthreads();
    for (int c = threadIdx.x; c < DHALF; c += 128) {
        float z = b2[c];
#pragma unroll
        for (int r = 0; r < 16; r++) z = fmaf(a[r], W2[(size_t)r * DHALF + c], z);
        float e = __expf(-fabsf(z));
        float l = __logf(1.f + e);
        float ls = (z >= 0.f) ? -l : (z - l);
        GK[(size_t)m * DHALF + c] = ls * INV_NORM_GK;
    }
}

// ======================================================================
// decay precompute (reads combined QK buffer) — 2 MUFU/element
// ======================================================================
__global__ void prep_kernel(const float* __restrict__ QK,
                            const float* __restrict__ GK,
                            __nv_bfloat16* __restrict__ QHo, __nv_bfloat16* __restrict__ QLo,
                            __nv_bfloat16* __restrict__ KHo, __nv_bfloat16* __restrict__ KLo,
                            __nv_bfloat16* __restrict__ KDHo, __nv_bfloat16* __restrict__ KDLo,
                            float* __restrict__ DEC)
{
    int g = blockIdx.x * blockDim.x + threadIdx.x;
    int col = g & (DHALF - 1);
    int bc  = g >> 10;
    int row0 = ((bc >> 4) * TT) + ((bc & 15) * CHUNK);
    size_t baseg = (size_t)row0 * DHALF + col;
    size_t baseq = (size_t)row0 * 2048 + col;

    float gs = 0.f;
#pragma unroll 4
    for (int i = 0; i < CHUNK; i++) gs += GK[baseg + (size_t)i * DHALF];
    float egs = __expf(gs);

    float gc = 0.f;
    for (int i = 0; i < CHUNK; i++) {
        size_t idx = baseg + (size_t)i * DHALF;
        size_t qdx = baseq + (size_t)i * 2048;
        gc += GK[idx];
        float eg = __expf(gc);
        float qd = QK[qdx] * eg;
        float kv = QK[qdx + 1024];
        float ke = __fdividef(kv, eg);
        float kd = ke * egs;
        __nv_bfloat16 qh = __float2bfloat16(qd);
        __nv_bfloat16 kh = __float2bfloat16(ke);
        __nv_bfloat16 dh = __float2bfloat16(kd);
        QHo[idx]  = qh; QLo[idx]  = __float2bfloat16(qd - __bfloat162float(qh));
        KHo[idx]  = kh; KLo[idx]  = __float2bfloat16(ke - __bfloat162float(kh));
        KDHo[idx] = dh; KDLo[idx] = __float2bfloat16(kd - __bfloat162float(dh));
    }
    DEC[(size_t)bc * DHALF + col] = egs;
}

// ======================================================================
// GroupNorm(256) * silu(g) -> bf16 hi/lo split
// ======================================================================
__global__ void norm_gate_kernel(const float* __restrict__ O,
                                 const float* __restrict__ G,
                                 __nv_bfloat16* __restrict__ PH,
                                 __nv_bfloat16* __restrict__ PL)
{
    int m = blockIdx.x, h = blockIdx.y;
    int tid = threadIdx.x;
    size_t idx = (size_t)m * DD + h * DV + tid;
    float v = O[idx];
    float s = v, s2 = v * v;
#pragma unroll
    for (int off = 16; off; off >>= 1) {
        s  += __shfl_xor_sync(0xFFFFFFFFu, s,  off);
        s2 += __shfl_xor_sync(0xFFFFFFFFu, s2, off);
    }
    __shared__ float ws[8], ws2[8];
    int w = tid >> 5, l = tid & 31;
    if (l == 0) { ws[w] = s; ws2[w] = s2; }
    __syncthreads();
    float ts = 0.f, ts2 = 0.f;
#pragma unroll
    for (int i = 0; i < 8; i++) { ts += ws[i]; ts2 += ws2[i]; }
    float mu = ts * (1.f / 256.f);
    float var = ts2 * (1.f / 256.f) - mu * mu;
    float nv = (v - mu) * rsqrtf(var + 1e-5f);
    float gt = G[idx];
    float sg = gt / (1.f + __expf(-gt));
    float val = sg * nv;
    __nv_bfloat16 hh = __float2bfloat16(val);
    PH[idx] = hh;
    PL[idx] = __float2bfloat16(val - __bfloat162float(hh));
}

// ======================================================================
extern "C" void kernel_launch(void* const* d_in, const int* in_sizes, int n_in,
                              void* d_out, int out_size)
{
    const float* x    = (const float*)d_in[0];
    const float* Wq   = (const float*)d_in[1];
    const float* Wk   = (const float*)d_in[2];
    const float* Wkg1 = (const float*)d_in[3];
    const float* Wkg2 = (const float*)d_in[4];
    const float* bkg2 = (const float*)d_in[5];
    const float* Wv   = (const float*)d_in[6];
    const float* Wg   = (const float*)d_in[7];
    const float* bg   = (const float*)d_in[8];
    const float* Wo   = (const float*)d_in[9];
    float* out = (float*)d_out;

    float *pQK, *pGK, *pKG1, *pDEC, *pG, *pO;
    __nv_bfloat16 *pXH, *pXL, *pWTH, *pWTL, *pPH, *pPL;
    __nv_bfloat16 *pQH, *pQL, *pKH, *pKL, *pKDH, *pKDL, *pVH, *pVL, *pAH, *pAL, *pSBH, *pSBL;
    cudaGetSymbolAddress((void**)&pQK,  g_QK);
    cudaGetSymbolAddress((void**)&pGK,  g_GK);
    cudaGetSymbolAddress((void**)&pKG1, g_KG1);
    cudaGetSymbolAddress((void**)&pDEC, g_DEC);
    cudaGetSymbolAddress((void**)&pG,   g_G);
    cudaGetSymbolAddress((void**)&pO,   g_O);
    cudaGetSymbolAddress((void**)&pXH,  g_XH);
    cudaGetSymbolAddress((void**)&pXL,  g_XL);
    cudaGetSymbolAddress((void**)&pWTH, g_WTH);
    cudaGetSymbolAddress((void**)&pWTL, g_WTL);
    cudaGetSymbolAddress((void**)&pPH,  g_PH);
    cudaGetSymbolAddress((void**)&pPL,  g_PL);
    cudaGetSymbolAddress((void**)&pQH,  g_QH);
    cudaGetSymbolAddress((void**)&pQL,  g_QL);
    cudaGetSymbolAddress((void**)&pKH,  g_KH);
    cudaGetSymbolAddress((void**)&pKL,  g_KL);
    cudaGetSymbolAddress((void**)&pKDH, g_KDH);
    cudaGetSymbolAddress((void**)&pKDL, g_KDL);
    cudaGetSymbolAddress((void**)&pVH,  g_VH);
    cudaGetSymbolAddress((void**)&pVL,  g_VL);
    cudaGetSymbolAddress((void**)&pAH,  g_AH);
    cudaGetSymbolAddress((void**)&pAL,  g_AL);
    cudaGetSymbolAddress((void**)&pSBH, g_SBH);
    cudaGetSymbolAddress((void**)&pSBL, g_SBL);

    cudaFuncSetAttribute(gemm3,        cudaFuncAttributeMaxDynamicSharedMemorySize, 196608);
    cudaFuncSetAttribute(akernel,      cudaFuncAttributeMaxDynamicSharedMemorySize, 131072);
    cudaFuncSetAttribute(state_kernel, cudaFuncAttributeMaxDynamicSharedMemorySize, 163840);
    cudaFuncSetAttribute(o_kernel,     cudaFuncAttributeMaxDynamicSharedMemorySize, 196608);

    dim3 tb(32, 8);
    int n4 = MROWS * DD / 4;

    // splits of x and all weights (combined WT buffer: Q|K*scale|V|G|O)
    xsplit<<<(n4 + 255) / 256, 256>>>((const float4*)x, pXH, pXL, n4);
    kg1_kernel<<<MROWS / 8, 256>>>(x, Wkg1, pKG1);
    wsplit_t<<<dim3(DHALF / 32, DD / 32), tb>>>(Wq, pWTH, pWTL, DD, DHALF, 0, 1.0f);
    wsplit_t<<<dim3(DHALF / 32, DD / 32), tb>>>(Wk, pWTH, pWTL, DD, DHALF, 1024, SCALING);
    wsplit_t<<<dim3(DD / 32, DD / 32), tb>>>(Wv, pWTH, pWTL, DD, DD, 2048, 1.0f);
    wsplit_t<<<dim3(DD / 32, DD / 32), tb>>>(Wg, pWTH, pWTL, DD, DD, 4096, 1.0f);
    wsplit_t<<<dim3(DD / 32, DD / 32), tb>>>(Wo, pWTH, pWTL, DD, DD, 6144, 1.0f);

    // fused Q+K projection (N=2048, all fp32 out)
    gemm3<<<dim3(2048 / 128, MROWS / 128), 512, 196608>>>(pXH, pXL, pWTH, pWTL,
        pQK, nullptr, nullptr, MROWS, 2048, DD, 0, 1.0f, nullptr);

    // gk + decay precompute
    gk_kernel<<<MROWS, 128>>>(pKG1, Wkg2, bkg2, pGK);
    prep_kernel<<<256, 256>>>(pQK, pGK, pQH, pQL, pKH, pKL, pKDH, pKDL, pDEC);

    // A chunks
    akernel<<<dim3(HH, NCH, BB), 256, 131072>>>(pQH, pQL, pKH, pKL, pAH, pAL);

    // fused V+G projection (N=4096; cols<2048 -> V bf16 split, cols>=2048 -> G fp32+bias)
    gemm3<<<dim3(4096 / 128, MROWS / 128), 512, 196608>>>(pXH, pXL,
        pWTH + (size_t)2048 * DD, pWTL + (size_t)2048 * DD,
        pG, pVH, pVL, MROWS, 4096, DD, 2048, 1.0f, bg);

    // serial state recurrence -> S blobs
    state_kernel<<<dim3(4, HH, BB), 256, 163840>>>(pKDH, pKDL, pVH, pVL, pDEC, pSBH, pSBL);

    // parallel O phase
    o_kernel<<<dim3(NCH * 4, HH, BB), 256, 196608>>>(pQH, pQL, pAH, pAL, pVH, pVL,
                                                     pSBH, pSBL, pO);

    // groupnorm + silu gate -> bf16 split
    norm_gate_kernel<<<dim3(MROWS, HH), 256>>>(pO, pG, pPH, pPL);

    // output projection (fp32 out)
    gemm3<<<dim3(DD / 128, MROWS / 128), 512, 196608>>>(pPH, pPL,
        pWTH + (size_t)6144 * DD, pWTL + (size_t)6144 * DD,
        out, nullptr, nullptr, MROWS, DD, DD, 0, 1.0f, nullptr);
}

// round 9
// speedup vs baseline: 1.0618x; 1.0618x over previous
#include <cuda_runtime.h>
#include <cuda_bf16.h>
#include <math.h>
#include <stdint.h>

// ---------------- problem constants ----------------
#define BB     4
#define TT     2048
#define DD     2048
#define HH     8
#define DK     128
#define DV     256
#define CHUNK  128
#define NCH    16
#define MROWS  (BB*TT)      // 8192
#define DHALF  (DD/2)       // 1024
#define SCALING 0.0625f
#define INV_NORM_GK (1.0f/16.0f)
#define NCHUNKS (BB*NCH*HH) // 512
#define NBLOBS  (BB*HH*4*NCH) // 2048 state blobs
#define WTROWS 8192         // combined transposed weights: Q|K|V|G|O

// ---------------- scratch ----------------
__device__ float g_QK [(size_t)MROWS * 2048];
__device__ float g_GK [(size_t)MROWS * DHALF];
__device__ float g_KG1[(size_t)MROWS * 16];
__device__ float g_DEC[(size_t)BB * NCH * DHALF];
__device__ float g_G  [(size_t)MROWS * DD];
__device__ float g_O  [(size_t)MROWS * DD];
__device__ __nv_bfloat16 g_XH [(size_t)MROWS * DD];
__device__ __nv_bfloat16 g_XL [(size_t)MROWS * DD];
__device__ __nv_bfloat16 g_WTH[(size_t)WTROWS * DD];
__device__ __nv_bfloat16 g_WTL[(size_t)WTROWS * DD];
__device__ __nv_bfloat16 g_PH [(size_t)MROWS * DD];
__device__ __nv_bfloat16 g_PL [(size_t)MROWS * DD];
__device__ __nv_bfloat16 g_QH [(size_t)MROWS * DHALF];
__device__ __nv_bfloat16 g_QL [(size_t)MROWS * DHALF];
__device__ __nv_bfloat16 g_KH [(size_t)MROWS * DHALF];
__device__ __nv_bfloat16 g_KL [(size_t)MROWS * DHALF];
__device__ __nv_bfloat16 g_KDH[(size_t)MROWS * DHALF];
__device__ __nv_bfloat16 g_KDL[(size_t)MROWS * DHALF];
__device__ __nv_bfloat16 g_VH [(size_t)MROWS * DD];
__device__ __nv_bfloat16 g_VL [(size_t)MROWS * DD];
__device__ __nv_bfloat16 g_AH [(size_t)NCHUNKS * CHUNK * CHUNK];
__device__ __nv_bfloat16 g_AL [(size_t)NCHUNKS * CHUNK * CHUNK];
__device__ __nv_bfloat16 g_SBH[(size_t)NBLOBS * 64 * 128];
__device__ __nv_bfloat16 g_SBL[(size_t)NBLOBS * 64 * 128];

// ================= helpers =================
__device__ __forceinline__ uint32_t smem_u32(const void* p) {
    uint32_t a;
    asm("{ .reg .u64 t; cvta.to.shared.u64 t, %1; cvt.u32.u64 %0, t; }" : "=r"(a) : "l"(p));
    return a;
}
__device__ __forceinline__ void cpasync16(uint32_t dst, const void* src) {
    asm volatile("cp.async.cg.shared.global [%0], [%1], 16;" :: "r"(dst), "l"(src) : "memory");
}
__device__ __forceinline__ void ldsm_x4(uint32_t* r, uint32_t addr) {
    asm volatile("ldmatrix.sync.aligned.m8n8.x4.shared.b16 {%0,%1,%2,%3}, [%4];"
                 : "=r"(r[0]), "=r"(r[1]), "=r"(r[2]), "=r"(r[3]) : "r"(addr));
}
__device__ __forceinline__ void mma16816(float* c, const uint32_t* a, const uint32_t* b) {
    asm volatile(
        "mma.sync.aligned.m16n8k16.row.col.f32.bf16.bf16.f32 "
        "{%0,%1,%2,%3}, {%4,%5,%6,%7}, {%8,%9}, {%0,%1,%2,%3};"
        : "+f"(c[0]), "+f"(c[1]), "+f"(c[2]), "+f"(c[3])
        : "r"(a[0]), "r"(a[1]), "r"(a[2]), "r"(a[3]), "r"(b[0]), "r"(b[1]));
}
static __device__ __forceinline__ uint32_t sw128(uint32_t o) { return o ^ ((o >> 3) & 0x70); }

// acc[MF][4][4] += A_tile @ B_tile^T over K=128 (2 sw128 K-subtiles)
template<int MF>
__device__ __forceinline__ void mma_combo(float (*acc)[4][4], uint32_t Ab, uint32_t abs_,
                                          uint32_t Bb, uint32_t bbs, int mw, int nw, int lane)
{
#pragma unroll
    for (int kb = 0; kb < 2; kb++) {
#pragma unroll
        for (int ks = 0; ks < 4; ks++) {
            uint32_t af[MF][4];
#pragma unroll
            for (int mf = 0; mf < MF; mf++) {
                int row = mw + mf * 16 + (lane & 15);
                uint32_t bo = (uint32_t)(row << 7) + (uint32_t)(ks << 5) + ((lane >> 4) << 4);
                ldsm_x4(af[mf], Ab + kb * abs_ + sw128(bo));
            }
            uint32_t bfr[4][2];
#pragma unroll
            for (int half = 0; half < 2; half++) {
                int i2 = lane >> 3;
                int row = nw + half * 16 + ((i2 >> 1) << 3) + (lane & 7);
                uint32_t bo = (uint32_t)(row << 7) + (uint32_t)(ks << 5) + ((i2 & 1) << 4);
                uint32_t r[4];
                ldsm_x4(r, Bb + kb * bbs + sw128(bo));
                bfr[half * 2][0] = r[0];     bfr[half * 2][1] = r[1];
                bfr[half * 2 + 1][0] = r[2]; bfr[half * 2 + 1][1] = r[3];
            }
#pragma unroll
            for (int mf = 0; mf < MF; mf++)
#pragma unroll
                for (int nf = 0; nf < 4; nf++)
                    mma16816(acc[mf][nf], af[mf], bfr[nf]);
        }
    }
}

// ======================================================================
// gemm3: shared-fragment bf16x3 GEMM, 3-stage cp.async pipeline,
// 256 threads (8 warps, 64x32 warp tiles, MF=4), ONE sync per chunk.
// Epilogue regions: cols < nsplit -> bf16 split (SHo/SLo, row stride nsplit);
// cols >= nsplit -> fp32 C (+bias), row stride N-nsplit.
// ======================================================================
__global__ __launch_bounds__(256, 1)
void gemm3(const __nv_bfloat16* __restrict__ AHp, const __nv_bfloat16* __restrict__ ALp,
           const __nv_bfloat16* __restrict__ BHp, const __nv_bfloat16* __restrict__ BLp,
           float* __restrict__ C, __nv_bfloat16* __restrict__ SHo, __nv_bfloat16* __restrict__ SLo,
           int M, int N, int K, int nsplit, float alpha, const float* __restrict__ bias)
{
    extern __shared__ char smem[];
    const uint32_t sbase = smem_u32(smem);
    const int tid = threadIdx.x;
    const int wid = tid >> 5, lane = tid & 31;
    const int m0 = blockIdx.y * 128, n0 = blockIdx.x * 128;
    const int mw = (wid & 1) * 64, nw = (wid >> 1) * 32;
    const int TOT = K >> 6;

    float acc[4][4][4];
#pragma unroll
    for (int i = 0; i < 4; i++)
#pragma unroll
        for (int j = 0; j < 4; j++)
#pragma unroll
            for (int l = 0; l < 4; l++) acc[i][j][l] = 0.f;

    auto issue = [&](int it) {
        const int k0 = it << 6;
        const uint32_t st = sbase + (uint32_t)(it % 3) * 65536u;
#pragma unroll
        for (int l = 0; l < 4; l++) {
            int c = tid + (l << 8);
            int row = c >> 3;
            uint32_t dst = sw128((uint32_t)(row << 7) + ((c & 7) << 4));
            int el = (c & 7) << 3;
            size_t ao = (size_t)(m0 + row) * K + k0 + el;
            size_t bo = (size_t)(n0 + row) * K + k0 + el;
            cpasync16(st + dst,         AHp + ao);
            cpasync16(st + 16384 + dst, ALp + ao);
            cpasync16(st + 32768 + dst, BHp + bo);
            cpasync16(st + 49152 + dst, BLp + bo);
        }
        asm volatile("cp.async.commit_group;" ::: "memory");
    };

    issue(0);
    if (TOT > 1) issue(1);
    for (int it = 0; it < TOT; it++) {
        if (it + 1 < TOT) {
            asm volatile("cp.async.wait_group 1;" ::: "memory");
        } else {
            asm volatile("cp.async.wait_group 0;" ::: "memory");
        }
        __syncthreads();
        const uint32_t st = sbase + (uint32_t)(it % 3) * 65536u;
#pragma unroll
        for (int ks = 0; ks < 4; ks++) {
            uint32_t afH[4][4], afL[4][4], bfH[4][2], bfL[4][2];
#pragma unroll
            for (int mf = 0; mf < 4; mf++) {
                int row = mw + mf * 16 + (lane & 15);
                uint32_t bo = (uint32_t)(row << 7) + (uint32_t)(ks << 5) + ((lane >> 4) << 4);
                uint32_t so = sw128(bo);
                ldsm_x4(afH[mf], st + so);
                ldsm_x4(afL[mf], st + 16384 + so);
            }
#pragma unroll
            for (int half = 0; half < 2; half++) {
                int i2 = lane >> 3;
                int row = nw + half * 16 + ((i2 >> 1) << 3) + (lane & 7);
                uint32_t bo = (uint32_t)(row << 7) + (uint32_t)(ks << 5) + ((i2 & 1) << 4);
                uint32_t so = sw128(bo);
                uint32_t r[4];
                ldsm_x4(r, st + 32768 + so);
                bfH[half * 2][0] = r[0];     bfH[half * 2][1] = r[1];
                bfH[half * 2 + 1][0] = r[2]; bfH[half * 2 + 1][1] = r[3];
                ldsm_x4(r, st + 49152 + so);
                bfL[half * 2][0] = r[0];     bfL[half * 2][1] = r[1];
                bfL[half * 2 + 1][0] = r[2]; bfL[half * 2 + 1][1] = r[3];
            }
#pragma unroll
            for (int mf = 0; mf < 4; mf++)
#pragma unroll
                for (int nf = 0; nf < 4; nf++) {
                    mma16816(acc[mf][nf], afH[mf], bfH[nf]);
                    mma16816(acc[mf][nf], afH[mf], bfL[nf]);
                    mma16816(acc[mf][nf], afL[mf], bfH[nf]);
                }
        }
        if (it + 2 < TOT) issue(it + 2);
    }

    const int rb = m0 + mw + (lane >> 2);
    const int cb = n0 + nw + ((lane & 3) << 1);
    const bool split_region = (n0 < nsplit);
    const int cstride = N - nsplit;
#pragma unroll
    for (int mf = 0; mf < 4; mf++) {
#pragma unroll
        for (int half = 0; half < 2; half++) {
            int row = rb + mf * 16 + half * 8;
#pragma unroll
            for (int nf = 0; nf < 4; nf++) {
                int col = cb + nf * 8;
                float vx = alpha * acc[mf][nf][half * 2 + 0];
                float vy = alpha * acc[mf][nf][half * 2 + 1];
                if (split_region) {
                    __nv_bfloat16 h0 = __float2bfloat16(vx);
                    __nv_bfloat16 h1 = __float2bfloat16(vy);
                    __nv_bfloat16 l0 = __float2bfloat16(vx - __bfloat162float(h0));
                    __nv_bfloat16 l1 = __float2bfloat16(vy - __bfloat162float(h1));
                    *(__nv_bfloat162*)(SHo + (size_t)row * nsplit + col) = __nv_bfloat162(h0, h1);
                    *(__nv_bfloat162*)(SLo + (size_t)row * nsplit + col) = __nv_bfloat162(l0, l1);
                } else {
                    int cc = col - nsplit;
                    if (bias) { vx += bias[cc]; vy += bias[cc + 1]; }
                    float2 v; v.x = vx; v.y = vy;
                    *(float2*)(C + (size_t)row * cstride + cc) = v;
                }
            }
        }
    }
}

// ======================================================================
// A-chunk kernel (verified): A = qd @ kexp^T, tril, split to bf16.
// ======================================================================
__global__ __launch_bounds__(256, 1)
void akernel(const __nv_bfloat16* __restrict__ QH, const __nv_bfloat16* __restrict__ QL,
             const __nv_bfloat16* __restrict__ KH, const __nv_bfloat16* __restrict__ KL,
             __nv_bfloat16* __restrict__ AH, __nv_bfloat16* __restrict__ AL)
{
    extern __shared__ char smemc[];
    const uint32_t sb = smem_u32(smemc);
    const uint32_t oQH = 0, oQL = 32768, oKH = 65536, oKL = 98304;
    const int tid = threadIdx.x;
    const int wid = tid >> 5, lane = tid & 31;
    const int h = blockIdx.x, ch = blockIdx.y, bb = blockIdx.z;
    const int m0 = bb * TT + ch * CHUNK;
    const int colQ = h * 128;
    const size_t chA = (size_t)((bb * NCH + ch) * HH + h) * 16384;

#pragma unroll
    for (int l = 0; l < 8; l++) {
        int idx = tid + (l << 8);
        int row = idx >> 4, u = idx & 15;
        int kb = u >> 3, sub = u & 7;
        uint32_t dst = (uint32_t)kb * 16384u + sw128((uint32_t)(row << 7) + (sub << 4));
        size_t so = (size_t)(m0 + row) * DHALF + colQ + kb * 64 + sub * 8;
        cpasync16(sb + oQH + dst, QH + so);
        cpasync16(sb + oQL + dst, QL + so);
        cpasync16(sb + oKH + dst, KH + so);
        cpasync16(sb + oKL + dst, KL + so);
    }
    asm volatile("cp.async.commit_group;" ::: "memory");
    asm volatile("cp.async.wait_group 0;" ::: "memory");
    __syncthreads();

    const int mw = (wid & 1) * 64, nw = (wid >> 1) * 32;
    float acc[4][4][4];
#pragma unroll
    for (int i = 0; i < 4; i++)
#pragma unroll
        for (int j = 0; j < 4; j++)
#pragma unroll
            for (int l = 0; l < 4; l++) acc[i][j][l] = 0.f;

    mma_combo<4>(acc, sb + oQH, 16384, sb + oKH, 16384, mw, nw, lane);
    mma_combo<4>(acc, sb + oQH, 16384, sb + oKL, 16384, mw, nw, lane);
    mma_combo<4>(acc, sb + oQL, 16384, sb + oKH, 16384, mw, nw, lane);

#pragma unroll
    for (int mf = 0; mf < 4; mf++) {
#pragma unroll
        for (int half = 0; half < 2; half++) {
            int i = mw + mf * 16 + half * 8 + (lane >> 2);
#pragma unroll
            for (int nf = 0; nf < 4; nf++) {
                int j = nw + nf * 8 + ((lane & 3) << 1);
                float v0 = (j     <= i) ? acc[mf][nf][half * 2 + 0] : 0.f;
                float v1 = (j + 1 <= i) ? acc[mf][nf][half * 2 + 1] : 0.f;
                __nv_bfloat16 h0 = __float2bfloat16(v0);
                __nv_bfloat16 h1 = __float2bfloat16(v1);
                __nv_bfloat16 l0 = __float2bfloat16(v0 - __bfloat162float(h0));
                __nv_bfloat16 l1 = __float2bfloat16(v1 - __bfloat162float(h1));
                size_t oi = chA + (size_t)i * 128 + j;
                *(__nv_bfloat162*)(AH + oi) = __nv_bfloat162(h0, h1);
                *(__nv_bfloat162*)(AL + oi) = __nv_bfloat162(l0, l1);
            }
        }
    }
}

// ======================================================================
// state_kernel: serial S recurrence per (b,h,dv64) -> pre-update S^T blobs
// ======================================================================
__global__ __launch_bounds__(256, 1)
void state_kernel(const __nv_bfloat16* __restrict__ KDH, const __nv_bfloat16* __restrict__ KDL,
                  const __nv_bfloat16* __restrict__ VH, const __nv_bfloat16* __restrict__ VL,
                  const float* __restrict__ DEC,
                  __nv_bfloat16* __restrict__ SBH, __nv_bfloat16* __restrict__ SBL)
{
    extern __shared__ char smemc[];
    const uint32_t sb = smem_u32(smemc);
    const uint32_t oKT = 0, oKTl = 32768, oVH = 65536, oVL = 81920;
    const uint32_t oSC = 98304, oSCl = 114688, oS32 = 131072;
    float* ST32 = (float*)(smemc + oS32);           // [n=64][d=128]
    __shared__ float dec[128];

    const int tid = threadIdx.x;
    const int wid = tid >> 5, lane = tid & 31;
    const int vsl = blockIdx.x, h = blockIdx.y, bb = blockIdx.z;
    const int colQ = h * 128;
    const int colV = h * 256 + vsl * 64;
    const int mw = (wid & 3) * 32, nw = (wid >> 2) * 32;
    const int blobbase = ((bb * HH + h) * 4 + vsl) * NCH;

    for (int i = tid; i < 8192; i += 256) ST32[i] = 0.f;

    for (int ch = 0; ch < NCH; ch++) {
        const int m0 = bb * TT + ch * CHUNK;
        __syncthreads();

#pragma unroll
        for (int l = 0; l < 32; l++) {
            int idx = tid + (l << 8);
            int j = idx >> 6, d = (idx & 63) << 1;
            uint32_t wv = *(const uint32_t*)(KDH + (size_t)(m0 + j) * DHALF + colQ + d);
            uint32_t wl = *(const uint32_t*)(KDL + (size_t)(m0 + j) * DHALF + colQ + d);
            uint32_t kbo = (uint32_t)(j >> 6) * 16384u;
            uint32_t off0 = kbo + sw128((uint32_t)(d << 7) + ((j & 63) << 1));
            uint32_t off1 = kbo + sw128((uint32_t)((d + 1) << 7) + ((j & 63) << 1));
            *(unsigned short*)(smemc + oKT  + off0) = (unsigned short)(wv & 0xffff);
            *(unsigned short*)(smemc + oKT  + off1) = (unsigned short)(wv >> 16);
            *(unsigned short*)(smemc + oKTl + off0) = (unsigned short)(wl & 0xffff);
            *(unsigned short*)(smemc + oKTl + off1) = (unsigned short)(wl >> 16);
        }
#pragma unroll
        for (int l = 0; l < 16; l++) {
            int idx = tid + (l << 8);
            int j = idx >> 5, n = (idx & 31) << 1;
            uint32_t wv = *(const uint32_t*)(VH + (size_t)(m0 + j) * DD + colV + n);
            uint32_t wl = *(const uint32_t*)(VL + (size_t)(m0 + j) * DD + colV + n);
            uint32_t kbo = (uint32_t)(j >> 6) * 8192u;
            uint32_t off0 = kbo + sw128((uint32_t)(n << 7) + ((j & 63) << 1));
            uint32_t off1 = kbo + sw128((uint32_t)((n + 1) << 7) + ((j & 63) << 1));
            *(unsigned short*)(smemc + oVH + off0) = (unsigned short)(wv & 0xffff);
            *(unsigned short*)(smemc + oVH + off1) = (unsigned short)(wv >> 16);
            *(unsigned short*)(smemc + oVL + off0) = (unsigned short)(wl & 0xffff);
            *(unsigned short*)(smemc + oVL + off1) = (unsigned short)(wl >> 16);
        }
        for (int i = tid; i < 8192; i += 256) {
            int n = i >> 7, d = i & 127;
            float v = ST32[i];
            __nv_bfloat16 hv = __float2bfloat16(v);
            __nv_bfloat16 lv = __float2bfloat16(v - __bfloat162float(hv));
            uint32_t off = (uint32_t)(d >> 6) * 8192u + sw128((uint32_t)(n << 7) + ((d & 63) << 1));
            *(__nv_bfloat16*)(smemc + oSC  + off) = hv;
            *(__nv_bfloat16*)(smemc + oSCl + off) = lv;
        }
        if (tid < 128) dec[tid] = DEC[(size_t)(bb * NCH + ch) * DHALF + colQ + tid];
        __syncthreads();

        {
            const float4* sH = (const float4*)(smemc + oSC);
            const float4* sL = (const float4*)(smemc + oSCl);
            float4* dH = (float4*)(SBH + (size_t)(blobbase + ch) * 8192);
            float4* dL = (float4*)(SBL + (size_t)(blobbase + ch) * 8192);
            for (int i = tid; i < 1024; i += 256) { dH[i] = sH[i]; dL[i] = sL[i]; }
        }

        float sacc[2][4][4];
#pragma unroll
        for (int i = 0; i < 2; i++)
#pragma unroll
            for (int j = 0; j < 4; j++)
#pragma unroll
                for (int l = 0; l < 4; l++) sacc[i][j][l] = 0.f;

        mma_combo<2>(sacc, sb + oKT,  16384, sb + oVH, 8192, mw, nw, lane);
        mma_combo<2>(sacc, sb + oKT,  16384, sb + oVL, 8192, mw, nw, lane);
        mma_combo<2>(sacc, sb + oKTl, 16384, sb + oVH, 8192, mw, nw, lane);

#pragma unroll
        for (int mf = 0; mf < 2; mf++) {
#pragma unroll
            for (int half = 0; half < 2; half++) {
                int d = mw + mf * 16 + half * 8 + (lane >> 2);
                float dv = dec[d];
#pragma unroll
                for (int nf = 0; nf < 4; nf++) {
                    int n = nw + nf * 8 + ((lane & 3) << 1);
                    int i0 = n * 128 + d, i1 = (n + 1) * 128 + d;
                    ST32[i0] = dv * ST32[i0] + sacc[mf][nf][half * 2 + 0];
                    ST32[i1] = dv * ST32[i1] + sacc[mf][nf][half * 2 + 1];
                }
            }
        }
    }
}

// ======================================================================
// o_kernel: fully parallel O phase. block per (b,h,ch,dv64).
// ======================================================================
__global__ __launch_bounds__(256, 1)
void o_kernel(const __nv_bfloat16* __restrict__ QH, const __nv_bfloat16* __restrict__ QL,
              const __nv_bfloat16* __restrict__ AH, const __nv_bfloat16* __restrict__ AL,
              const __nv_bfloat16* __restrict__ VH, const __nv_bfloat16* __restrict__ VL,
              const __nv_bfloat16* __restrict__ SBH, const __nv_bfloat16* __restrict__ SBL,
              float* __restrict__ O)
{
    extern __shared__ char smemc[];
    const uint32_t sb = smem_u32(smemc);
    const uint32_t oQH = 0, oQL = 32768, oAH = 65536, oAL = 98304;
    const uint32_t oVH = 131072, oVL = 147456, oSH = 163840, oSL = 180224;

    const int tid = threadIdx.x;
    const int wid = tid >> 5, lane = tid & 31;
    const int ch = blockIdx.x >> 2, vsl = blockIdx.x & 3;
    const int h = blockIdx.y, bb = blockIdx.z;
    const int m0 = bb * TT + ch * CHUNK;
    const int colQ = h * 128;
    const int colV = h * 256 + vsl * 64;
    const size_t chA = (size_t)((bb * NCH + ch) * HH + h) * 16384;
    const size_t blob = (size_t)(((bb * HH + h) * 4 + vsl) * NCH + ch) * 8192;
    const int mw = (wid & 3) * 32, nw = (wid >> 2) * 32;

#pragma unroll
    for (int l = 0; l < 8; l++) {
        int idx = tid + (l << 8);
        int row = idx >> 4, u = idx & 15;
        int kb = u >> 3, sub = u & 7;
        uint32_t dst = (uint32_t)kb * 16384u + sw128((uint32_t)(row << 7) + (sub << 4));
        size_t so = (size_t)(m0 + row) * DHALF + colQ + kb * 64 + sub * 8;
        cpasync16(sb + oQH + dst, QH + so);
        cpasync16(sb + oQL + dst, QL + so);
        size_t sa = chA + (size_t)row * 128 + kb * 64 + sub * 8;
        cpasync16(sb + oAH + dst, AH + sa);
        cpasync16(sb + oAL + dst, AL + sa);
    }
#pragma unroll
    for (int l = 0; l < 4; l++) {
        int i = tid + (l << 8);
        cpasync16(sb + oSH + (i << 4), SBH + blob + (size_t)i * 8);
        cpasync16(sb + oSL + (i << 4), SBL + blob + (size_t)i * 8);
    }
    asm volatile("cp.async.commit_group;" ::: "memory");

#pragma unroll
    for (int l = 0; l < 16; l++) {
        int idx = tid + (l << 8);
        int j = idx >> 5, n = (idx & 31) << 1;
        uint32_t wv = *(const uint32_t*)(VH + (size_t)(m0 + j) * DD + colV + n);
        uint32_t wl = *(const uint32_t*)(VL + (size_t)(m0 + j) * DD + colV + n);
        uint32_t kbo = (uint32_t)(j >> 6) * 8192u;
        uint32_t off0 = kbo + sw128((uint32_t)(n << 7) + ((j & 63) << 1));
        uint32_t off1 = kbo + sw128((uint32_t)((n + 1) << 7) + ((j & 63) << 1));
        *(unsigned short*)(smemc + oVH + off0) = (unsigned short)(wv & 0xffff);
        *(unsigned short*)(smemc + oVH + off1) = (unsigned short)(wv >> 16);
        *(unsigned short*)(smemc + oVL + off0) = (unsigned short)(wl & 0xffff);
        *(unsigned short*)(smemc + oVL + off1) = (unsigned short)(wl >> 16);
    }
    asm volatile("cp.async.wait_group 0;" ::: "memory");
    __syncthreads();

    float acc[2][4][4];
#pragma unroll
    for (int i = 0; i < 2; i++)
#pragma unroll
        for (int j = 0; j < 4; j++)
#pragma unroll
            for (int l = 0; l < 4; l++) acc[i][j][l] = 0.f;

    mma_combo<2>(acc, sb + oAH, 16384, sb + oVH, 8192, mw, nw, lane);
    mma_combo<2>(acc, sb + oAH, 16384, sb + oVL, 8192, mw, nw, lane);
    mma_combo<2>(acc, sb + oAL, 16384, sb + oVH, 8192, mw, nw, lane);
    mma_combo<2>(acc, sb + oQH, 16384, sb + oSH, 8192, mw, nw, lane);
    mma_combo<2>(acc, sb + oQH, 16384, sb + oSL, 8192, mw, nw, lane);
    mma_combo<2>(acc, sb + oQL, 16384, sb + oSH, 8192, mw, nw, lane);

#pragma unroll
    for (int mf = 0; mf < 2; mf++) {
#pragma unroll
        for (int half = 0; half < 2; half++) {
            int row = m0 + mw + mf * 16 + half * 8 + (lane >> 2);
#pragma unroll
            for (int nf = 0; nf < 4; nf++) {
                int col = colV + nw + nf * 8 + ((lane & 3) << 1);
                float2 v;
                v.x = acc[mf][nf][half * 2 + 0];
                v.y = acc[mf][nf][half * 2 + 1];
                *(float2*)&O[(size_t)row * DD + col] = v;
            }
        }
    }
}

// ======================================================================
// split x -> bf16 hi/lo
// ======================================================================
__global__ void xsplit(const float4* __restrict__ X, __nv_bfloat16* __restrict__ H,
                       __nv_bfloat16* __restrict__ L, int n4)
{
    int i = blockIdx.x * blockDim.x + threadIdx.x;
    if (i >= n4) return;
    float4 v = X[i];
    __nv_bfloat16 h0 = __float2bfloat16(v.x), h1 = __float2bfloat16(v.y);
    __nv_bfloat16 h2 = __float2bfloat16(v.z), h3 = __float2bfloat16(v.w);
    __nv_bfloat16 l0 = __float2bfloat16(v.x - __bfloat162float(h0));
    __nv_bfloat16 l1 = __float2bfloat16(v.y - __bfloat162float(h1));
    __nv_bfloat16 l2 = __float2bfloat16(v.z - __bfloat162float(h2));
    __nv_bfloat16 l3 = __float2bfloat16(v.w - __bfloat162float(h3));
    __nv_bfloat162* Hp = (__nv_bfloat162*)H;
    __nv_bfloat162* Lp = (__nv_bfloat162*)L;
    Hp[i * 2]     = __nv_bfloat162(h0, h1);
    Hp[i * 2 + 1] = __nv_bfloat162(h2, h3);
    Lp[i * 2]     = __nv_bfloat162(l0, l1);
    Lp[i * 2 + 1] = __nv_bfloat162(l2, l3);
}

// ======================================================================
// transpose W [K,N] -> combined WT buffer rows [rowoff..rowoff+N), x alpha
// ======================================================================
__global__ void wsplit_t(const float* __restrict__ W, __nv_bfloat16* __restrict__ Th,
                         __nv_bfloat16* __restrict__ Tl, int K, int N, int rowoff, float alpha)
{
    __shared__ float t[32][33];
    const int n0 = blockIdx.x * 32, k0 = blockIdx.y * 32;
    const int tx = threadIdx.x, ty = threadIdx.y;
#pragma unroll
    for (int i = 0; i < 4; i++) {
        int k = ty + i * 8;
        t[k][tx] = W[(size_t)(k0 + k) * N + n0 + tx];
    }
    __syncthreads();
#pragma unroll
    for (int i = 0; i < 4; i++) {
        int n = ty + i * 8;
        float v = t[tx][n] * alpha;
        __nv_bfloat16 h = __float2bfloat16(v);
        size_t oi = (size_t)(rowoff + n0 + n) * K + k0 + tx;
        Th[oi] = h;
        Tl[oi] = __float2bfloat16(v - __bfloat162float(h));
    }
}

// ======================================================================
// kg1: out[M,16] = x @ Wkg1. warp per row.
// ======================================================================
__global__ void kg1_kernel(const float* __restrict__ x, const float* __restrict__ W1,
                           float* __restrict__ out)
{
    const int wid = threadIdx.x >> 5, lane = threadIdx.x & 31;
    const int row = blockIdx.x * 8 + wid;
    const float* xp = x + (size_t)row * DD;
    float acc[16];
#pragma unroll
    for (int c = 0; c < 16; c++) acc[c] = 0.f;
    for (int k = lane; k < DD; k += 32) {
        float xv = xp[k];
        const float4* wp = (const float4*)(W1 + (size_t)k * 16);
        float4 w0 = wp[0], w1 = wp[1], w2 = wp[2], w3 = wp[3];
        acc[0]  += xv * w0.x; acc[1]  += xv * w0.y; acc[2]  += xv * w0.z; acc[3]  += xv * w0.w;
        acc[4]  += xv * w1.x; acc[5]  += xv * w1.y; acc[6]  += xv * w1.z; acc[7]  += xv * w1.w;
        acc[8]  += xv * w2.x; acc[9]  += xv * w2.y; acc[10] += xv * w2.z; acc[11] += xv * w2.w;
        acc[12] += xv * w3.x; acc[13] += xv * w3.y; acc[14] += xv * w3.z; acc[15] += xv * w3.w;
    }
#pragma unroll
    for (int c = 0; c < 16; c++) {
        float v = acc[c];
#pragma unroll
        for (int off = 16; off; off >>= 1) v += __shfl_xor_sync(0xFFFFFFFFu, v, off);
        if (lane == 0) out[(size_t)row * 16 + c] = v;
    }
}

// ======================================================================
// gk = log_sigmoid(KG1 @ Wkg2 + bkg2) / 16   (fast intrinsics)
// ======================================================================
__global__ void gk_kernel(const float* __restrict__ KG1,
                          const float* __restrict__ W2,
                          const float* __restrict__ b2,
                          float* __restrict__ GK)
{
    __shared__ float a[16];
    int m = blockIdx.x;
    if (threadIdx.x < 16) a[threadIdx.x] = KG1[(size_t)m * 16 + threadIdx.x];
    __syncthreads();
    for (int c = threadIdx.x; c < DHALF; c += 128) {
        float z = b2[c];
#pragma unroll
        for (int r = 0; r < 16; r++) z = fmaf(a[r], W2[(size_t)r * DHALF + c], z);
        float e = __expf(-fabsf(z));
        float l = __logf(1.f + e);
        float ls = (z >= 0.f) ? -l : (z - l);
        GK[(size_t)m * DHALF + c] = ls * INV_NORM_GK;
    }
}

// ======================================================================
// decay precompute (reads combined QK buffer) — 2 MUFU/element
// ======================================================================
__global__ void prep_kernel(const float* __restrict__ QK,
                            const float* __restrict__ GK,
                            __nv_bfloat16* __restrict__ QHo, __nv_bfloat16* __restrict__ QLo,
                            __nv_bfloat16* __restrict__ KHo, __nv_bfloat16* __restrict__ KLo,
                            __nv_bfloat16* __restrict__ KDHo, __nv_bfloat16* __restrict__ KDLo,
                            float* __restrict__ DEC)
{
    int g = blockIdx.x * blockDim.x + threadIdx.x;
    int col = g & (DHALF - 1);
    int bc  = g >> 10;
    int row0 = ((bc >> 4) * TT) + ((bc & 15) * CHUNK);
    size_t baseg = (size_t)row0 * DHALF + col;
    size_t baseq = (size_t)row0 * 2048 + col;

    float gs = 0.f;
#pragma unroll 4
    for (int i = 0; i < CHUNK; i++) gs += GK[baseg + (size_t)i * DHALF];
    float egs = __expf(gs);

    float gc = 0.f;
    for (int i = 0; i < CHUNK; i++) {
        size_t idx = baseg + (size_t)i * DHALF;
        size_t qdx = baseq + (size_t)i * 2048;
        gc += GK[idx];
        float eg = __expf(gc);
        float qd = QK[qdx] * eg;
        float kv = QK[qdx + 1024];
        float ke = __fdividef(kv, eg);
        float kd = ke * egs;
        __nv_bfloat16 qh = __float2bfloat16(qd);
        __nv_bfloat16 kh = __float2bfloat16(ke);
        __nv_bfloat16 dh = __float2bfloat16(kd);
        QHo[idx]  = qh; QLo[idx]  = __float2bfloat16(qd - __bfloat162float(qh));
        KHo[idx]  = kh; KLo[idx]  = __float2bfloat16(ke - __bfloat162float(kh));
        KDHo[idx] = dh; KDLo[idx] = __float2bfloat16(kd - __bfloat162float(dh));
    }
    DEC[(size_t)bc * DHALF + col] = egs;
}

// ======================================================================
// GroupNorm(256) * silu(g) -> bf16 hi/lo split
// ======================================================================
__global__ void norm_gate_kernel(const float* __restrict__ O,
                                 const float* __restrict__ G,
                                 __nv_bfloat16* __restrict__ PH,
                                 __nv_bfloat16* __restrict__ PL)
{
    int m = blockIdx.x, h = blockIdx.y;
    int tid = threadIdx.x;
    size_t idx = (size_t)m * DD + h * DV + tid;
    float v = O[idx];
    float s = v, s2 = v * v;
#pragma unroll
    for (int off = 16; off; off >>= 1) {
        s  += __shfl_xor_sync(0xFFFFFFFFu, s,  off);
        s2 += __shfl_xor_sync(0xFFFFFFFFu, s2, off);
    }
    __shared__ float ws[8], ws2[8];
    int w = tid >> 5, l = tid & 31;
    if (l == 0) { ws[w] = s; ws2[w] = s2; }
    __syncthreads();
    float ts = 0.f, ts2 = 0.f;
#pragma unroll
    for (int i = 0; i < 8; i++) { ts += ws[i]; ts2 += ws2[i]; }
    float mu = ts * (1.f / 256.f);
    float var = ts2 * (1.f / 256.f) - mu * mu;
    float nv = (v - mu) * rsqrtf(var + 1e-5f);
    float gt = G[idx];
    float sg = gt / (1.f + __expf(-gt));
    float val = sg * nv;
    __nv_bfloat16 hh = __float2bfloat16(val);
    PH[idx] = hh;
    PL[idx] = __float2bfloat16(val - __bfloat162float(hh));
}

// ======================================================================
extern "C" void kernel_launch(void* const* d_in, const int* in_sizes, int n_in,
                              void* d_out, int out_size)
{
    const float* x    = (const float*)d_in[0];
    const float* Wq   = (const float*)d_in[1];
    const float* Wk   = (const float*)d_in[2];
    const float* Wkg1 = (const float*)d_in[3];
    const float* Wkg2 = (const float*)d_in[4];
    const float* bkg2 = (const float*)d_in[5];
    const float* Wv   = (const float*)d_in[6];
    const float* Wg   = (const float*)d_in[7];
    const float* bg   = (const float*)d_in[8];
    const float* Wo   = (const float*)d_in[9];
    float* out = (float*)d_out;

    float *pQK, *pGK, *pKG1, *pDEC, *pG, *pO;
    __nv_bfloat16 *pXH, *pXL, *pWTH, *pWTL, *pPH, *pPL;
    __nv_bfloat16 *pQH, *pQL, *pKH, *pKL, *pKDH, *pKDL, *pVH, *pVL, *pAH, *pAL, *pSBH, *pSBL;
    cudaGetSymbolAddress((void**)&pQK,  g_QK);
    cudaGetSymbolAddress((void**)&pGK,  g_GK);
    cudaGetSymbolAddress((void**)&pKG1, g_KG1);
    cudaGetSymbolAddress((void**)&pDEC, g_DEC);
    cudaGetSymbolAddress((void**)&pG,   g_G);
    cudaGetSymbolAddress((void**)&pO,   g_O);
    cudaGetSymbolAddress((void**)&pXH,  g_XH);
    cudaGetSymbolAddress((void**)&pXL,  g_XL);
    cudaGetSymbolAddress((void**)&pWTH, g_WTH);
    cudaGetSymbolAddress((void**)&pWTL, g_WTL);
    cudaGetSymbolAddress((void**)&pPH,  g_PH);
    cudaGetSymbolAddress((void**)&pPL,  g_PL);
    cudaGetSymbolAddress((void**)&pQH,  g_QH);
    cudaGetSymbolAddress((void**)&pQL,  g_QL);
    cudaGetSymbolAddress((void**)&pKH,  g_KH);
    cudaGetSymbolAddress((void**)&pKL,  g_KL);
    cudaGetSymbolAddress((void**)&pKDH, g_KDH);
    cudaGetSymbolAddress((void**)&pKDL, g_KDL);
    cudaGetSymbolAddress((void**)&pVH,  g_VH);
    cudaGetSymbolAddress((void**)&pVL,  g_VL);
    cudaGetSymbolAddress((void**)&pAH,  g_AH);
    cudaGetSymbolAddress((void**)&pAL,  g_AL);
    cudaGetSymbolAddress((void**)&pSBH, g_SBH);
    cudaGetSymbolAddress((void**)&pSBL, g_SBL);

    cudaFuncSetAttribute(gemm3,        cudaFuncAttributeMaxDynamicSharedMemorySize, 196608);
    cudaFuncSetAttribute(akernel,      cudaFuncAttributeMaxDynamicSharedMemorySize, 131072);
    cudaFuncSetAttribute(state_kernel, cudaFuncAttributeMaxDynamicSharedMemorySize, 163840);
    cudaFuncSetAttribute(o_kernel,     cudaFuncAttributeMaxDynamicSharedMemorySize, 196608);

    dim3 tb(32, 8);
    int n4 = MROWS * DD / 4;

    // splits of x and all weights (combined WT buffer: Q|K*scale|V|G|O)
    xsplit<<<(n4 + 255) / 256, 256>>>((const float4*)x, pXH, pXL, n4);
    kg1_kernel<<<MROWS / 8, 256>>>(x, Wkg1, pKG1);
    wsplit_t<<<dim3(DHALF / 32, DD / 32), tb>>>(Wq, pWTH, pWTL, DD, DHALF, 0, 1.0f);
    wsplit_t<<<dim3(DHALF / 32, DD / 32), tb>>>(Wk, pWTH, pWTL, DD, DHALF, 1024, SCALING);
    wsplit_t<<<dim3(DD / 32, DD / 32), tb>>>(Wv, pWTH, pWTL, DD, DD, 2048, 1.0f);
    wsplit_t<<<dim3(DD / 32, DD / 32), tb>>>(Wg, pWTH, pWTL, DD, DD, 4096, 1.0f);
    wsplit_t<<<dim3(DD / 32, DD / 32), tb>>>(Wo, pWTH, pWTL, DD, DD, 6144, 1.0f);

    // fused Q+K projection (N=2048, all fp32 out)
    gemm3<<<dim3(2048 / 128, MROWS / 128), 256, 196608>>>(pXH, pXL, pWTH, pWTL,
        pQK, nullptr, nullptr, MROWS, 2048, DD, 0, 1.0f, nullptr);

    // gk + decay precompute
    gk_kernel<<<MROWS, 128>>>(pKG1, Wkg2, bkg2, pGK);
    prep_kernel<<<256, 256>>>(pQK, pGK, pQH, pQL, pKH, pKL, pKDH, pKDL, pDEC);

    // A chunks
    akernel<<<dim3(HH, NCH, BB), 256, 131072>>>(pQH, pQL, pKH, pKL, pAH, pAL);

    // fused V+G projection (N=4096; cols<2048 -> V bf16 split, cols>=2048 -> G fp32+bias)
    gemm3<<<dim3(4096 / 128, MROWS / 128), 256, 196608>>>(pXH, pXL,
        pWTH + (size_t)2048 * DD, pWTL + (size_t)2048 * DD,
        pG, pVH, pVL, MROWS, 4096, DD, 2048, 1.0f, bg);

    // serial state recurrence -> S blobs
    state_kernel<<<dim3(4, HH, BB), 256, 163840>>>(pKDH, pKDL, pVH, pVL, pDEC, pSBH, pSBL);

    // parallel O phase
    o_kernel<<<dim3(NCH * 4, HH, BB), 256, 196608>>>(pQH, pQL, pAH, pAL, pVH, pVL,
                                                     pSBH, pSBL, pO);

    // groupnorm + silu gate -> bf16 split
    norm_gate_kernel<<<dim3(MROWS, HH), 256>>>(pO, pG, pPH, pPL);

    // output projection (fp32 out)
    gemm3<<<dim3(DD / 128, MROWS / 128), 256, 196608>>>(pPH, pPL,
        pWTH + (size_t)6144 * DD, pWTL + (size_t)6144 * DD,
        out, nullptr, nullptr, MROWS, DD, DD, 0, 1.0f, nullptr);
}

// round 10
// speedup vs baseline: 1.3288x; 1.2515x over previous
#include <cuda_runtime.h>
#include <cuda_bf16.h>
#include <cuda_fp16.h>
#include <math.h>
#include <stdint.h>

// ---------------- problem constants ----------------
#define BB     4
#define TT     2048
#define DD     2048
#define HH     8
#define DK     128
#define DV     256
#define CHUNK  128
#define NCH    16
#define MROWS  (BB*TT)      // 8192
#define DHALF  (DD/2)       // 1024
#define SCALING 0.0625f
#define INV_NORM_GK (1.0f/16.0f)
#define NCHUNKS (BB*NCH*HH) // 512
#define NBLOBS  (BB*HH*4*NCH) // 2048 state blobs
#define WTROWS 8192         // combined transposed weights: Q|K|V|G|O

// ---------------- scratch ----------------
__device__ float g_QK [(size_t)MROWS * 2048];
__device__ float g_GK [(size_t)MROWS * DHALF];
__device__ float g_KG1[(size_t)MROWS * 16];
__device__ float g_DEC[(size_t)BB * NCH * DHALF];
__device__ float g_G  [(size_t)MROWS * DD];
__device__ float g_O  [(size_t)MROWS * DD];
__device__ __half g_XH [(size_t)MROWS * DD];
__device__ __half g_WTH[(size_t)WTROWS * DD];
__device__ __half g_WTL[(size_t)WTROWS * DD];
__device__ __half g_PH [(size_t)MROWS * DD];
__device__ __nv_bfloat16 g_QH [(size_t)MROWS * DHALF];
__device__ __nv_bfloat16 g_QL [(size_t)MROWS * DHALF];
__device__ __nv_bfloat16 g_KH [(size_t)MROWS * DHALF];
__device__ __nv_bfloat16 g_KL [(size_t)MROWS * DHALF];
__device__ __nv_bfloat16 g_KDH[(size_t)MROWS * DHALF];
__device__ __nv_bfloat16 g_KDL[(size_t)MROWS * DHALF];
__device__ __nv_bfloat16 g_VH [(size_t)MROWS * DD];
__device__ __nv_bfloat16 g_VL [(size_t)MROWS * DD];
__device__ __nv_bfloat16 g_AH [(size_t)NCHUNKS * CHUNK * CHUNK];
__device__ __nv_bfloat16 g_AL [(size_t)NCHUNKS * CHUNK * CHUNK];
__device__ __nv_bfloat16 g_SBH[(size_t)NBLOBS * 64 * 128];
__device__ __nv_bfloat16 g_SBL[(size_t)NBLOBS * 64 * 128];

// ================= helpers =================
__device__ __forceinline__ uint32_t smem_u32(const void* p) {
    uint32_t a;
    asm("{ .reg .u64 t; cvta.to.shared.u64 t, %1; cvt.u32.u64 %0, t; }" : "=r"(a) : "l"(p));
    return a;
}
__device__ __forceinline__ void cpasync16(uint32_t dst, const void* src) {
    asm volatile("cp.async.cg.shared.global [%0], [%1], 16;" :: "r"(dst), "l"(src) : "memory");
}
__device__ __forceinline__ void ldsm_x4(uint32_t* r, uint32_t addr) {
    asm volatile("ldmatrix.sync.aligned.m8n8.x4.shared.b16 {%0,%1,%2,%3}, [%4];"
                 : "=r"(r[0]), "=r"(r[1]), "=r"(r[2]), "=r"(r[3]) : "r"(addr));
}
__device__ __forceinline__ void mma16816(float* c, const uint32_t* a, const uint32_t* b) {
    asm volatile(
        "mma.sync.aligned.m16n8k16.row.col.f32.bf16.bf16.f32 "
        "{%0,%1,%2,%3}, {%4,%5,%6,%7}, {%8,%9}, {%0,%1,%2,%3};"
        : "+f"(c[0]), "+f"(c[1]), "+f"(c[2]), "+f"(c[3])
        : "r"(a[0]), "r"(a[1]), "r"(a[2]), "r"(a[3]), "r"(b[0]), "r"(b[1]));
}
__device__ __forceinline__ void mma16816h(float* c, const uint32_t* a, const uint32_t* b) {
    asm volatile(
        "mma.sync.aligned.m16n8k16.row.col.f32.f16.f16.f32 "
        "{%0,%1,%2,%3}, {%4,%5,%6,%7}, {%8,%9}, {%0,%1,%2,%3};"
        : "+f"(c[0]), "+f"(c[1]), "+f"(c[2]), "+f"(c[3])
        : "r"(a[0]), "r"(a[1]), "r"(a[2]), "r"(a[3]), "r"(b[0]), "r"(b[1]));
}
static __device__ __forceinline__ uint32_t sw128(uint32_t o) { return o ^ ((o >> 3) & 0x70); }

// acc[MF][4][4] += A_tile @ B_tile^T over K=128 (2 sw128 K-subtiles) [bf16]
template<int MF>
__device__ __forceinline__ void mma_combo(float (*acc)[4][4], uint32_t Ab, uint32_t abs_,
                                          uint32_t Bb, uint32_t bbs, int mw, int nw, int lane)
{
#pragma unroll
    for (int kb = 0; kb < 2; kb++) {
#pragma unroll
        for (int ks = 0; ks < 4; ks++) {
            uint32_t af[MF][4];
#pragma unroll
            for (int mf = 0; mf < MF; mf++) {
                int row = mw + mf * 16 + (lane & 15);
                uint32_t bo = (uint32_t)(row << 7) + (uint32_t)(ks << 5) + ((lane >> 4) << 4);
                ldsm_x4(af[mf], Ab + kb * abs_ + sw128(bo));
            }
            uint32_t bfr[4][2];
#pragma unroll
            for (int half = 0; half < 2; half++) {
                int i2 = lane >> 3;
                int row = nw + half * 16 + ((i2 >> 1) << 3) + (lane & 7);
                uint32_t bo = (uint32_t)(row << 7) + (uint32_t)(ks << 5) + ((i2 & 1) << 4);
                uint32_t r[4];
                ldsm_x4(r, Bb + kb * bbs + sw128(bo));
                bfr[half * 2][0] = r[0];     bfr[half * 2][1] = r[1];
                bfr[half * 2 + 1][0] = r[2]; bfr[half * 2 + 1][1] = r[3];
            }
#pragma unroll
            for (int mf = 0; mf < MF; mf++)
#pragma unroll
                for (int nf = 0; nf < 4; nf++)
                    mma16816(acc[mf][nf], af[mf], bfr[nf]);
        }
    }
}

// ======================================================================
// gemm2h: fp16 2-pass GEMM. C = alpha*(Ah @ (Bh+Bl)^T). 3-stage pipeline,
// per stage 3 tiles (AH, BH, BL) = 48KB. 256 threads, 64x32 warp tiles.
// Epilogue regions: cols < nsplit -> bf16 split (SHo/SLo, stride nsplit);
// cols >= nsplit -> fp32 C (+bias), stride N-nsplit.
// ======================================================================
__global__ __launch_bounds__(256, 1)
void gemm2h(const __half* __restrict__ AHp,
            const __half* __restrict__ BHp, const __half* __restrict__ BLp,
            float* __restrict__ C, __nv_bfloat16* __restrict__ SHo, __nv_bfloat16* __restrict__ SLo,
            int M, int N, int K, int nsplit, float alpha, const float* __restrict__ bias)
{
    extern __shared__ char smem[];
    const uint32_t sbase = smem_u32(smem);
    const int tid = threadIdx.x;
    const int wid = tid >> 5, lane = tid & 31;
    const int m0 = blockIdx.y * 128, n0 = blockIdx.x * 128;
    const int mw = (wid & 1) * 64, nw = (wid >> 1) * 32;
    const int TOT = K >> 6;

    float acc[4][4][4];
#pragma unroll
    for (int i = 0; i < 4; i++)
#pragma unroll
        for (int j = 0; j < 4; j++)
#pragma unroll
            for (int l = 0; l < 4; l++) acc[i][j][l] = 0.f;

    auto issue = [&](int it) {
        const int k0 = it << 6;
        const uint32_t st = sbase + (uint32_t)(it % 3) * 49152u;
#pragma unroll
        for (int l = 0; l < 4; l++) {
            int c = tid + (l << 8);
            int row = c >> 3;
            uint32_t dst = sw128((uint32_t)(row << 7) + ((c & 7) << 4));
            int el = (c & 7) << 3;
            size_t ao = (size_t)(m0 + row) * K + k0 + el;
            size_t bo = (size_t)(n0 + row) * K + k0 + el;
            cpasync16(st + dst,         AHp + ao);
            cpasync16(st + 16384 + dst, BHp + bo);
            cpasync16(st + 32768 + dst, BLp + bo);
        }
        asm volatile("cp.async.commit_group;" ::: "memory");
    };

    issue(0);
    if (TOT > 1) issue(1);
    for (int it = 0; it < TOT; it++) {
        if (it + 1 < TOT) {
            asm volatile("cp.async.wait_group 1;" ::: "memory");
        } else {
            asm volatile("cp.async.wait_group 0;" ::: "memory");
        }
        __syncthreads();
        const uint32_t st = sbase + (uint32_t)(it % 3) * 49152u;
#pragma unroll
        for (int ks = 0; ks < 4; ks++) {
            uint32_t afH[4][4], bfH[4][2], bfL[4][2];
#pragma unroll
            for (int mf = 0; mf < 4; mf++) {
                int row = mw + mf * 16 + (lane & 15);
                uint32_t bo = (uint32_t)(row << 7) + (uint32_t)(ks << 5) + ((lane >> 4) << 4);
                ldsm_x4(afH[mf], st + sw128(bo));
            }
#pragma unroll
            for (int half = 0; half < 2; half++) {
                int i2 = lane >> 3;
                int row = nw + half * 16 + ((i2 >> 1) << 3) + (lane & 7);
                uint32_t bo = (uint32_t)(row << 7) + (uint32_t)(ks << 5) + ((i2 & 1) << 4);
                uint32_t so = sw128(bo);
                uint32_t r[4];
                ldsm_x4(r, st + 16384 + so);
                bfH[half * 2][0] = r[0];     bfH[half * 2][1] = r[1];
                bfH[half * 2 + 1][0] = r[2]; bfH[half * 2 + 1][1] = r[3];
                ldsm_x4(r, st + 32768 + so);
                bfL[half * 2][0] = r[0];     bfL[half * 2][1] = r[1];
                bfL[half * 2 + 1][0] = r[2]; bfL[half * 2 + 1][1] = r[3];
            }
#pragma unroll
            for (int mf = 0; mf < 4; mf++)
#pragma unroll
                for (int nf = 0; nf < 4; nf++) {
                    mma16816h(acc[mf][nf], afH[mf], bfH[nf]);
                    mma16816h(acc[mf][nf], afH[mf], bfL[nf]);
                }
        }
        if (it + 2 < TOT) issue(it + 2);
    }

    const int rb = m0 + mw + (lane >> 2);
    const int cb = n0 + nw + ((lane & 3) << 1);
    const bool split_region = (n0 < nsplit);
    const int cstride = N - nsplit;
#pragma unroll
    for (int mf = 0; mf < 4; mf++) {
#pragma unroll
        for (int half = 0; half < 2; half++) {
            int row = rb + mf * 16 + half * 8;
#pragma unroll
            for (int nf = 0; nf < 4; nf++) {
                int col = cb + nf * 8;
                float vx = alpha * acc[mf][nf][half * 2 + 0];
                float vy = alpha * acc[mf][nf][half * 2 + 1];
                if (split_region) {
                    __nv_bfloat16 h0 = __float2bfloat16(vx);
                    __nv_bfloat16 h1 = __float2bfloat16(vy);
                    __nv_bfloat16 l0 = __float2bfloat16(vx - __bfloat162float(h0));
                    __nv_bfloat16 l1 = __float2bfloat16(vy - __bfloat162float(h1));
                    *(__nv_bfloat162*)(SHo + (size_t)row * nsplit + col) = __nv_bfloat162(h0, h1);
                    *(__nv_bfloat162*)(SLo + (size_t)row * nsplit + col) = __nv_bfloat162(l0, l1);
                } else {
                    int cc = col - nsplit;
                    if (bias) { vx += bias[cc]; vy += bias[cc + 1]; }
                    float2 v; v.x = vx; v.y = vy;
                    *(float2*)(C + (size_t)row * cstride + cc) = v;
                }
            }
        }
    }
}

// ======================================================================
// A-chunk kernel (verified, bf16 3-pass): A = qd @ kexp^T, tril, split.
// ======================================================================
__global__ __launch_bounds__(256, 1)
void akernel(const __nv_bfloat16* __restrict__ QH, const __nv_bfloat16* __restrict__ QL,
             const __nv_bfloat16* __restrict__ KH, const __nv_bfloat16* __restrict__ KL,
             __nv_bfloat16* __restrict__ AH, __nv_bfloat16* __restrict__ AL)
{
    extern __shared__ char smemc[];
    const uint32_t sb = smem_u32(smemc);
    const uint32_t oQH = 0, oQL = 32768, oKH = 65536, oKL = 98304;
    const int tid = threadIdx.x;
    const int wid = tid >> 5, lane = tid & 31;
    const int h = blockIdx.x, ch = blockIdx.y, bb = blockIdx.z;
    const int m0 = bb * TT + ch * CHUNK;
    const int colQ = h * 128;
    const size_t chA = (size_t)((bb * NCH + ch) * HH + h) * 16384;

#pragma unroll
    for (int l = 0; l < 8; l++) {
        int idx = tid + (l << 8);
        int row = idx >> 4, u = idx & 15;
        int kb = u >> 3, sub = u & 7;
        uint32_t dst = (uint32_t)kb * 16384u + sw128((uint32_t)(row << 7) + (sub << 4));
        size_t so = (size_t)(m0 + row) * DHALF + colQ + kb * 64 + sub * 8;
        cpasync16(sb + oQH + dst, QH + so);
        cpasync16(sb + oQL + dst, QL + so);
        cpasync16(sb + oKH + dst, KH + so);
        cpasync16(sb + oKL + dst, KL + so);
    }
    asm volatile("cp.async.commit_group;" ::: "memory");
    asm volatile("cp.async.wait_group 0;" ::: "memory");
    __syncthreads();

    const int mw = (wid & 1) * 64, nw = (wid >> 1) * 32;
    float acc[4][4][4];
#pragma unroll
    for (int i = 0; i < 4; i++)
#pragma unroll
        for (int j = 0; j < 4; j++)
#pragma unroll
            for (int l = 0; l < 4; l++) acc[i][j][l] = 0.f;

    mma_combo<4>(acc, sb + oQH, 16384, sb + oKH, 16384, mw, nw, lane);
    mma_combo<4>(acc, sb + oQH, 16384, sb + oKL, 16384, mw, nw, lane);
    mma_combo<4>(acc, sb + oQL, 16384, sb + oKH, 16384, mw, nw, lane);

#pragma unroll
    for (int mf = 0; mf < 4; mf++) {
#pragma unroll
        for (int half = 0; half < 2; half++) {
            int i = mw + mf * 16 + half * 8 + (lane >> 2);
#pragma unroll
            for (int nf = 0; nf < 4; nf++) {
                int j = nw + nf * 8 + ((lane & 3) << 1);
                float v0 = (j     <= i) ? acc[mf][nf][half * 2 + 0] : 0.f;
                float v1 = (j + 1 <= i) ? acc[mf][nf][half * 2 + 1] : 0.f;
                __nv_bfloat16 h0 = __float2bfloat16(v0);
                __nv_bfloat16 h1 = __float2bfloat16(v1);
                __nv_bfloat16 l0 = __float2bfloat16(v0 - __bfloat162float(h0));
                __nv_bfloat16 l1 = __float2bfloat16(v1 - __bfloat162float(h1));
                size_t oi = chA + (size_t)i * 128 + j;
                *(__nv_bfloat162*)(AH + oi) = __nv_bfloat162(h0, h1);
                *(__nv_bfloat162*)(AL + oi) = __nv_bfloat162(l0, l1);
            }
        }
    }
}

// ======================================================================
// state_kernel: serial S recurrence per (b,h,dv64) -> pre-update S^T blobs
// ======================================================================
__global__ __launch_bounds__(256, 1)
void state_kernel(const __nv_bfloat16* __restrict__ KDH, const __nv_bfloat16* __restrict__ KDL,
                  const __nv_bfloat16* __restrict__ VH, const __nv_bfloat16* __restrict__ VL,
                  const float* __restrict__ DEC,
                  __nv_bfloat16* __restrict__ SBH, __nv_bfloat16* __restrict__ SBL)
{
    extern __shared__ char smemc[];
    const uint32_t sb = smem_u32(smemc);
    const uint32_t oKT = 0, oKTl = 32768, oVH = 65536, oVL = 81920;
    const uint32_t oSC = 98304, oSCl = 114688, oS32 = 131072;
    float* ST32 = (float*)(smemc + oS32);           // [n=64][d=128]
    __shared__ float dec[128];

    const int tid = threadIdx.x;
    const int wid = tid >> 5, lane = tid & 31;
    const int vsl = blockIdx.x, h = blockIdx.y, bb = blockIdx.z;
    const int colQ = h * 128;
    const int colV = h * 256 + vsl * 64;
    const int mw = (wid & 3) * 32, nw = (wid >> 2) * 32;
    const int blobbase = ((bb * HH + h) * 4 + vsl) * NCH;

    for (int i = tid; i < 8192; i += 256) ST32[i] = 0.f;

    for (int ch = 0; ch < NCH; ch++) {
        const int m0 = bb * TT + ch * CHUNK;
        __syncthreads();

#pragma unroll
        for (int l = 0; l < 32; l++) {
            int idx = tid + (l << 8);
            int j = idx >> 6, d = (idx & 63) << 1;
            uint32_t wv = *(const uint32_t*)(KDH + (size_t)(m0 + j) * DHALF + colQ + d);
            uint32_t wl = *(const uint32_t*)(KDL + (size_t)(m0 + j) * DHALF + colQ + d);
            uint32_t kbo = (uint32_t)(j >> 6) * 16384u;
            uint32_t off0 = kbo + sw128((uint32_t)(d << 7) + ((j & 63) << 1));
            uint32_t off1 = kbo + sw128((uint32_t)((d + 1) << 7) + ((j & 63) << 1));
            *(unsigned short*)(smemc + oKT  + off0) = (unsigned short)(wv & 0xffff);
            *(unsigned short*)(smemc + oKT  + off1) = (unsigned short)(wv >> 16);
            *(unsigned short*)(smemc + oKTl + off0) = (unsigned short)(wl & 0xffff);
            *(unsigned short*)(smemc + oKTl + off1) = (unsigned short)(wl >> 16);
        }
#pragma unroll
        for (int l = 0; l < 16; l++) {
            int idx = tid + (l << 8);
            int j = idx >> 5, n = (idx & 31) << 1;
            uint32_t wv = *(const uint32_t*)(VH + (size_t)(m0 + j) * DD + colV + n);
            uint32_t wl = *(const uint32_t*)(VL + (size_t)(m0 + j) * DD + colV + n);
            uint32_t kbo = (uint32_t)(j >> 6) * 8192u;
            uint32_t off0 = kbo + sw128((uint32_t)(n << 7) + ((j & 63) << 1));
            uint32_t off1 = kbo + sw128((uint32_t)((n + 1) << 7) + ((j & 63) << 1));
            *(unsigned short*)(smemc + oVH + off0) = (unsigned short)(wv & 0xffff);
            *(unsigned short*)(smemc + oVH + off1) = (unsigned short)(wv >> 16);
            *(unsigned short*)(smemc + oVL + off0) = (unsigned short)(wl & 0xffff);
            *(unsigned short*)(smemc + oVL + off1) = (unsigned short)(wl >> 16);
        }
        for (int i = tid; i < 8192; i += 256) {
            int n = i >> 7, d = i & 127;
            float v = ST32[i];
            __nv_bfloat16 hv = __float2bfloat16(v);
            __nv_bfloat16 lv = __float2bfloat16(v - __bfloat162float(hv));
            uint32_t off = (uint32_t)(d >> 6) * 8192u + sw128((uint32_t)(n << 7) + ((d & 63) << 1));
            *(__nv_bfloat16*)(smemc + oSC  + off) = hv;
            *(__nv_bfloat16*)(smemc + oSCl + off) = lv;
        }
        if (tid < 128) dec[tid] = DEC[(size_t)(bb * NCH + ch) * DHALF + colQ + tid];
        __syncthreads();

        {
            const float4* sH = (const float4*)(smemc + oSC);
            const float4* sL = (const float4*)(smemc + oSCl);
            float4* dH = (float4*)(SBH + (size_t)(blobbase + ch) * 8192);
            float4* dL = (float4*)(SBL + (size_t)(blobbase + ch) * 8192);
            for (int i = tid; i < 1024; i += 256) { dH[i] = sH[i]; dL[i] = sL[i]; }
        }

        float sacc[2][4][4];
#pragma unroll
        for (int i = 0; i < 2; i++)
#pragma unroll
            for (int j = 0; j < 4; j++)
#pragma unroll
                for (int l = 0; l < 4; l++) sacc[i][j][l] = 0.f;

        mma_combo<2>(sacc, sb + oKT,  16384, sb + oVH, 8192, mw, nw, lane);
        mma_combo<2>(sacc, sb + oKT,  16384, sb + oVL, 8192, mw, nw, lane);
        mma_combo<2>(sacc, sb + oKTl, 16384, sb + oVH, 8192, mw, nw, lane);

#pragma unroll
        for (int mf = 0; mf < 2; mf++) {
#pragma unroll
            for (int half = 0; half < 2; half++) {
                int d = mw + mf * 16 + half * 8 + (lane >> 2);
                float dv = dec[d];
#pragma unroll
                for (int nf = 0; nf < 4; nf++) {
                    int n = nw + nf * 8 + ((lane & 3) << 1);
                    int i0 = n * 128 + d, i1 = (n + 1) * 128 + d;
                    ST32[i0] = dv * ST32[i0] + sacc[mf][nf][half * 2 + 0];
                    ST32[i1] = dv * ST32[i1] + sacc[mf][nf][half * 2 + 1];
                }
            }
        }
    }
}

// ======================================================================
// o_kernel: fully parallel O phase. block per (b,h,ch,dv64).
// ======================================================================
__global__ __launch_bounds__(256, 1)
void o_kernel(const __nv_bfloat16* __restrict__ QH, const __nv_bfloat16* __restrict__ QL,
              const __nv_bfloat16* __restrict__ AH, const __nv_bfloat16* __restrict__ AL,
              const __nv_bfloat16* __restrict__ VH, const __nv_bfloat16* __restrict__ VL,
              const __nv_bfloat16* __restrict__ SBH, const __nv_bfloat16* __restrict__ SBL,
              float* __restrict__ O)
{
    extern __shared__ char smemc[];
    const uint32_t sb = smem_u32(smemc);
    const uint32_t oQH = 0, oQL = 32768, oAH = 65536, oAL = 98304;
    const uint32_t oVH = 131072, oVL = 147456, oSH = 163840, oSL = 180224;

    const int tid = threadIdx.x;
    const int wid = tid >> 5, lane = tid & 31;
    const int ch = blockIdx.x >> 2, vsl = blockIdx.x & 3;
    const int h = blockIdx.y, bb = blockIdx.z;
    const int m0 = bb * TT + ch * CHUNK;
    const int colQ = h * 128;
    const int colV = h * 256 + vsl * 64;
    const size_t chA = (size_t)((bb * NCH + ch) * HH + h) * 16384;
    const size_t blob = (size_t)(((bb * HH + h) * 4 + vsl) * NCH + ch) * 8192;
    const int mw = (wid & 3) * 32, nw = (wid >> 2) * 32;

#pragma unroll
    for (int l = 0; l < 8; l++) {
        int idx = tid + (l << 8);
        int row = idx >> 4, u = idx & 15;
        int kb = u >> 3, sub = u & 7;
        uint32_t dst = (uint32_t)kb * 16384u + sw128((uint32_t)(row << 7) + (sub << 4));
        size_t so = (size_t)(m0 + row) * DHALF + colQ + kb * 64 + sub * 8;
        cpasync16(sb + oQH + dst, QH + so);
        cpasync16(sb + oQL + dst, QL + so);
        size_t sa = chA + (size_t)row * 128 + kb * 64 + sub * 8;
        cpasync16(sb + oAH + dst, AH + sa);
        cpasync16(sb + oAL + dst, AL + sa);
    }
#pragma unroll
    for (int l = 0; l < 4; l++) {
        int i = tid + (l << 8);
        cpasync16(sb + oSH + (i << 4), SBH + blob + (size_t)i * 8);
        cpasync16(sb + oSL + (i << 4), SBL + blob + (size_t)i * 8);
    }
    asm volatile("cp.async.commit_group;" ::: "memory");

#pragma unroll
    for (int l = 0; l < 16; l++) {
        int idx = tid + (l << 8);
        int j = idx >> 5, n = (idx & 31) << 1;
        uint32_t wv = *(const uint32_t*)(VH + (size_t)(m0 + j) * DD + colV + n);
        uint32_t wl = *(const uint32_t*)(VL + (size_t)(m0 + j) * DD + colV + n);
        uint32_t kbo = (uint32_t)(j >> 6) * 8192u;
        uint32_t off0 = kbo + sw128((uint32_t)(n << 7) + ((j & 63) << 1));
        uint32_t off1 = kbo + sw128((uint32_t)((n + 1) << 7) + ((j & 63) << 1));
        *(unsigned short*)(smemc + oVH + off0) = (unsigned short)(wv & 0xffff);
        *(unsigned short*)(smemc + oVH + off1) = (unsigned short)(wv >> 16);
        *(unsigned short*)(smemc + oVL + off0) = (unsigned short)(wl & 0xffff);
        *(unsigned short*)(smemc + oVL + off1) = (unsigned short)(wl >> 16);
    }
    asm volatile("cp.async.wait_group 0;" ::: "memory");
    __syncthreads();

    float acc[2][4][4];
#pragma unroll
    for (int i = 0; i < 2; i++)
#pragma unroll
        for (int j = 0; j < 4; j++)
#pragma unroll
            for (int l = 0; l < 4; l++) acc[i][j][l] = 0.f;

    mma_combo<2>(acc, sb + oAH, 16384, sb + oVH, 8192, mw, nw, lane);
    mma_combo<2>(acc, sb + oAH, 16384, sb + oVL, 8192, mw, nw, lane);
    mma_combo<2>(acc, sb + oAL, 16384, sb + oVH, 8192, mw, nw, lane);
    mma_combo<2>(acc, sb + oQH, 16384, sb + oSH, 8192, mw, nw, lane);
    mma_combo<2>(acc, sb + oQH, 16384, sb + oSL, 8192, mw, nw, lane);
    mma_combo<2>(acc, sb + oQL, 16384, sb + oSH, 8192, mw, nw, lane);

#pragma unroll
    for (int mf = 0; mf < 2; mf++) {
#pragma unroll
        for (int half = 0; half < 2; half++) {
            int row = m0 + mw + mf * 16 + half * 8 + (lane >> 2);
#pragma unroll
            for (int nf = 0; nf < 4; nf++) {
                int col = colV + nw + nf * 8 + ((lane & 3) << 1);
                float2 v;
                v.x = acc[mf][nf][half * 2 + 0];
                v.y = acc[mf][nf][half * 2 + 1];
                *(float2*)&O[(size_t)row * DD + col] = v;
            }
        }
    }
}

// ======================================================================
// x -> fp16 (A operand needs hi only)
// ======================================================================
__global__ void xhalf(const float4* __restrict__ X, __half* __restrict__ H, int n4)
{
    int i = blockIdx.x * blockDim.x + threadIdx.x;
    if (i >= n4) return;
    float4 v = X[i];
    __half2* Hp = (__half2*)H;
    Hp[i * 2]     = __floats2half2_rn(v.x, v.y);
    Hp[i * 2 + 1] = __floats2half2_rn(v.z, v.w);
}

// ======================================================================
// transpose W [K,N] -> combined WT fp16 hi/lo rows [rowoff..), x alpha
// ======================================================================
__global__ void wsplit_t(const float* __restrict__ W, __half* __restrict__ Th,
                         __half* __restrict__ Tl, int K, int N, int rowoff, float alpha)
{
    __shared__ float t[32][33];
    const int n0 = blockIdx.x * 32, k0 = blockIdx.y * 32;
    const int tx = threadIdx.x, ty = threadIdx.y;
#pragma unroll
    for (int i = 0; i < 4; i++) {
        int k = ty + i * 8;
        t[k][tx] = W[(size_t)(k0 + k) * N + n0 + tx];
    }
    __syncthreads();
#pragma unroll
    for (int i = 0; i < 4; i++) {
        int n = ty + i * 8;
        float v = t[tx][n] * alpha;
        __half h = __float2half(v);
        size_t oi = (size_t)(rowoff + n0 + n) * K + k0 + tx;
        Th[oi] = h;
        Tl[oi] = __float2half(v - __half2float(h));
    }
}

// ======================================================================
// kg1: out[M,16] = x @ Wkg1. warp per row.
// ======================================================================
__global__ void kg1_kernel(const float* __restrict__ x, const float* __restrict__ W1,
                           float* __restrict__ out)
{
    const int wid = threadIdx.x >> 5, lane = threadIdx.x & 31;
    const int row = blockIdx.x * 8 + wid;
    const float* xp = x + (size_t)row * DD;
    float acc[16];
#pragma unroll
    for (int c = 0; c < 16; c++) acc[c] = 0.f;
    for (int k = lane; k < DD; k += 32) {
        float xv = xp[k];
        const float4* wp = (const float4*)(W1 + (size_t)k * 16);
        float4 w0 = wp[0], w1 = wp[1], w2 = wp[2], w3 = wp[3];
        acc[0]  += xv * w0.x; acc[1]  += xv * w0.y; acc[2]  += xv * w0.z; acc[3]  += xv * w0.w;
        acc[4]  += xv * w1.x; acc[5]  += xv * w1.y; acc[6]  += xv * w1.z; acc[7]  += xv * w1.w;
        acc[8]  += xv * w2.x; acc[9]  += xv * w2.y; acc[10] += xv * w2.z; acc[11] += xv * w2.w;
        acc[12] += xv * w3.x; acc[13] += xv * w3.y; acc[14] += xv * w3.z; acc[15] += xv * w3.w;
    }
#pragma unroll
    for (int c = 0; c < 16; c++) {
        float v = acc[c];
#pragma unroll
        for (int off = 16; off; off >>= 1) v += __shfl_xor_sync(0xFFFFFFFFu, v, off);
        if (lane == 0) out[(size_t)row * 16 + c] = v;
    }
}

// ======================================================================
// gk = log_sigmoid(KG1 @ Wkg2 + bkg2) / 16
// ======================================================================
__global__ void gk_kernel(const float* __restrict__ KG1,
                          const float* __restrict__ W2,
                          const float* __restrict__ b2,
                          float* __restrict__ GK)
{
    __shared__ float a[16];
    int m = blockIdx.x;
    if (threadIdx.x < 16) a[threadIdx.x] = KG1[(size_t)m * 16 + threadIdx.x];
    __syncthreads();
    for (int c = threadIdx.x; c < DHALF; c += 128) {
        float z = b2[c];
#pragma unroll
        for (int r = 0; r < 16; r++) z = fmaf(a[r], W2[(size_t)r * DHALF + c], z);
        float e = __expf(-fabsf(z));
        float l = __logf(1.f + e);
        float ls = (z >= 0.f) ? -l : (z - l);
        GK[(size_t)m * DHALF + c] = ls * INV_NORM_GK;
    }
}

// ======================================================================
// decay precompute (reads combined QK buffer)
// ======================================================================
__global__ void prep_kernel(const float* __restrict__ QK,
                            const float* __restrict__ GK,
                            __nv_bfloat16* __restrict__ QHo, __nv_bfloat16* __restrict__ QLo,
                            __nv_bfloat16* __restrict__ KHo, __nv_bfloat16* __restrict__ KLo,
                            __nv_bfloat16* __restrict__ KDHo, __nv_bfloat16* __restrict__ KDLo,
                            float* __restrict__ DEC)
{
    int g = blockIdx.x * blockDim.x + threadIdx.x;
    int col = g & (DHALF - 1);
    int bc  = g >> 10;
    int row0 = ((bc >> 4) * TT) + ((bc & 15) * CHUNK);
    size_t baseg = (size_t)row0 * DHALF + col;
    size_t baseq = (size_t)row0 * 2048 + col;

    float gs = 0.f;
#pragma unroll 4
    for (int i = 0; i < CHUNK; i++) gs += GK[baseg + (size_t)i * DHALF];
    float egs = __expf(gs);

    float gc = 0.f;
    for (int i = 0; i < CHUNK; i++) {
        size_t idx = baseg + (size_t)i * DHALF;
        size_t qdx = baseq + (size_t)i * 2048;
        gc += GK[idx];
        float eg = __expf(gc);
        float qd = QK[qdx] * eg;
        float kv = QK[qdx + 1024];
        float ke = __fdividef(kv, eg);
        float kd = ke * egs;
        __nv_bfloat16 qh = __float2bfloat16(qd);
        __nv_bfloat16 kh = __float2bfloat16(ke);
        __nv_bfloat16 dh = __float2bfloat16(kd);
        QHo[idx]  = qh; QLo[idx]  = __float2bfloat16(qd - __bfloat162float(qh));
        KHo[idx]  = kh; KLo[idx]  = __float2bfloat16(ke - __bfloat162float(kh));
        KDHo[idx] = dh; KDLo[idx] = __float2bfloat16(kd - __bfloat162float(dh));
    }
    DEC[(size_t)bc * DHALF + col] = egs;
}

// ======================================================================
// GroupNorm(256) * silu(g) -> fp16 (A operand of Wo gemm)
// ======================================================================
__global__ void norm_gate_kernel(const float* __restrict__ O,
                                 const float* __restrict__ G,
                                 __half* __restrict__ PH)
{
    int m = blockIdx.x, h = blockIdx.y;
    int tid = threadIdx.x;
    size_t idx = (size_t)m * DD + h * DV + tid;
    float v = O[idx];
    float s = v, s2 = v * v;
#pragma unroll
    for (int off = 16; off; off >>= 1) {
        s  += __shfl_xor_sync(0xFFFFFFFFu, s,  off);
        s2 += __shfl_xor_sync(0xFFFFFFFFu, s2, off);
    }
    __shared__ float ws[8], ws2[8];
    int w = tid >> 5, l = tid & 31;
    if (l == 0) { ws[w] = s; ws2[w] = s2; }
    __syncthreads();
    float ts = 0.f, ts2 = 0.f;
#pragma unroll
    for (int i = 0; i < 8; i++) { ts += ws[i]; ts2 += ws2[i]; }
    float mu = ts * (1.f / 256.f);
    float var = ts2 * (1.f / 256.f) - mu * mu;
    float nv = (v - mu) * rsqrtf(var + 1e-5f);
    float gt = G[idx];
    float sg = gt / (1.f + __expf(-gt));
    PH[idx] = __float2half(sg * nv);
}

// ======================================================================
extern "C" void kernel_launch(void* const* d_in, const int* in_sizes, int n_in,
                              void* d_out, int out_size)
{
    const float* x    = (const float*)d_in[0];
    const float* Wq   = (const float*)d_in[1];
    const float* Wk   = (const float*)d_in[2];
    const float* Wkg1 = (const float*)d_in[3];
    const float* Wkg2 = (const float*)d_in[4];
    const float* bkg2 = (const float*)d_in[5];
    const float* Wv   = (const float*)d_in[6];
    const float* Wg   = (const float*)d_in[7];
    const float* bg   = (const float*)d_in[8];
    const float* Wo   = (const float*)d_in[9];
    float* out = (float*)d_out;

    float *pQK, *pGK, *pKG1, *pDEC, *pG, *pO;
    __half *pXH, *pWTH, *pWTL, *pPH;
    __nv_bfloat16 *pQH, *pQL, *pKH, *pKL, *pKDH, *pKDL, *pVH, *pVL, *pAH, *pAL, *pSBH, *pSBL;
    cudaGetSymbolAddress((void**)&pQK,  g_QK);
    cudaGetSymbolAddress((void**)&pGK,  g_GK);
    cudaGetSymbolAddress((void**)&pKG1, g_KG1);
    cudaGetSymbolAddress((void**)&pDEC, g_DEC);
    cudaGetSymbolAddress((void**)&pG,   g_G);
    cudaGetSymbolAddress((void**)&pO,   g_O);
    cudaGetSymbolAddress((void**)&pXH,  g_XH);
    cudaGetSymbolAddress((void**)&pWTH, g_WTH);
    cudaGetSymbolAddress((void**)&pWTL, g_WTL);
    cudaGetSymbolAddress((void**)&pPH,  g_PH);
    cudaGetSymbolAddress((void**)&pQH,  g_QH);
    cudaGetSymbolAddress((void**)&pQL,  g_QL);
    cudaGetSymbolAddress((void**)&pKH,  g_KH);
    cudaGetSymbolAddress((void**)&pKL,  g_KL);
    cudaGetSymbolAddress((void**)&pKDH, g_KDH);
    cudaGetSymbolAddress((void**)&pKDL, g_KDL);
    cudaGetSymbolAddress((void**)&pVH,  g_VH);
    cudaGetSymbolAddress((void**)&pVL,  g_VL);
    cudaGetSymbolAddress((void**)&pAH,  g_AH);
    cudaGetSymbolAddress((void**)&pAL,  g_AL);
    cudaGetSymbolAddress((void**)&pSBH, g_SBH);
    cudaGetSymbolAddress((void**)&pSBL, g_SBL);

    cudaFuncSetAttribute(gemm2h,       cudaFuncAttributeMaxDynamicSharedMemorySize, 147456);
    cudaFuncSetAttribute(akernel,      cudaFuncAttributeMaxDynamicSharedMemorySize, 131072);
    cudaFuncSetAttribute(state_kernel, cudaFuncAttributeMaxDynamicSharedMemorySize, 163840);
    cudaFuncSetAttribute(o_kernel,     cudaFuncAttributeMaxDynamicSharedMemorySize, 196608);

    dim3 tb(32, 8);
    int n4 = MROWS * DD / 4;

    // x -> fp16 ; weights -> combined WT fp16 hi/lo (Q|K*scale|V|G|O)
    xhalf<<<(n4 + 255) / 256, 256>>>((const float4*)x, pXH, n4);
    kg1_kernel<<<MROWS / 8, 256>>>(x, Wkg1, pKG1);
    wsplit_t<<<dim3(DHALF / 32, DD / 32), tb>>>(Wq, pWTH, pWTL, DD, DHALF, 0, 1.0f);
    wsplit_t<<<dim3(DHALF / 32, DD / 32), tb>>>(Wk, pWTH, pWTL, DD, DHALF, 1024, SCALING);
    wsplit_t<<<dim3(DD / 32, DD / 32), tb>>>(Wv, pWTH, pWTL, DD, DD, 2048, 1.0f);
    wsplit_t<<<dim3(DD / 32, DD / 32), tb>>>(Wg, pWTH, pWTL, DD, DD, 4096, 1.0f);
    wsplit_t<<<dim3(DD / 32, DD / 32), tb>>>(Wo, pWTH, pWTL, DD, DD, 6144, 1.0f);

    // fused Q+K projection (N=2048, fp32 out)
    gemm2h<<<dim3(2048 / 128, MROWS / 128), 256, 147456>>>(pXH, pWTH, pWTL,
        pQK, nullptr, nullptr, MROWS, 2048, DD, 0, 1.0f, nullptr);

    // gk + decay precompute
    gk_kernel<<<MROWS, 128>>>(pKG1, Wkg2, bkg2, pGK);
    prep_kernel<<<256, 256>>>(pQK, pGK, pQH, pQL, pKH, pKL, pKDH, pKDL, pDEC);

    // A chunks
    akernel<<<dim3(HH, NCH, BB), 256, 131072>>>(pQH, pQL, pKH, pKL, pAH, pAL);

    // fused V+G projection (N=4096; cols<2048 -> V bf16 split, cols>=2048 -> G fp32+bias)
    gemm2h<<<dim3(4096 / 128, MROWS / 128), 256, 147456>>>(pXH,
        pWTH + (size_t)2048 * DD, pWTL + (size_t)2048 * DD,
        pG, pVH, pVL, MROWS, 4096, DD, 2048, 1.0f, bg);

    // serial state recurrence -> S blobs
    state_kernel<<<dim3(4, HH, BB), 256, 163840>>>(pKDH, pKDL, pVH, pVL, pDEC, pSBH, pSBL);

    // parallel O phase
    o_kernel<<<dim3(NCH * 4, HH, BB), 256, 196608>>>(pQH, pQL, pAH, pAL, pVH, pVL,
                                                     pSBH, pSBL, pO);

    // groupnorm + silu gate -> fp16
    norm_gate_kernel<<<dim3(MROWS, HH), 256>>>(pO, pG, pPH);

    // output projection (fp32 out)
    gemm2h<<<dim3(DD / 128, MROWS / 128), 256, 147456>>>(pPH,
        pWTH + (size_t)6144 * DD, pWTL + (size_t)6144 * DD,
        out, nullptr, nullptr, MROWS, DD, DD, 0, 1.0f, nullptr);
}

// round 11
// speedup vs baseline: 1.3509x; 1.0166x over previous
#include <cuda_runtime.h>
#include <cuda_bf16.h>
#include <cuda_fp16.h>
#include <math.h>
#include <stdint.h>

// ---------------- problem constants ----------------
#define BB     4
#define TT     2048
#define DD     2048
#define HH     8
#define DK     128
#define DV     256
#define CHUNK  128
#define NCH    16
#define MROWS  (BB*TT)      // 8192
#define DHALF  (DD/2)       // 1024
#define SCALING 0.0625f
#define INV_NORM_GK (1.0f/16.0f)
#define NCHUNKS (BB*NCH*HH) // 512
#define NBLOBS  (BB*HH*4*NCH) // 2048 state blobs
#define WTROWS 8192

// ---------------- scratch ----------------
__device__ float g_QK [(size_t)MROWS * 2048];
__device__ float g_GK [(size_t)MROWS * DHALF];
__device__ float g_KG1[(size_t)MROWS * 16];
__device__ float g_DEC[(size_t)BB * NCH * DHALF];
__device__ float g_G  [(size_t)MROWS * DD];
__device__ float g_O  [(size_t)MROWS * DD];
__device__ float g_U  [(size_t)NBLOBS * 8192];
__device__ __half g_XH [(size_t)MROWS * DD];
__device__ __half g_WTH[(size_t)WTROWS * DD];
__device__ __half g_WTL[(size_t)WTROWS * DD];
__device__ __half g_PH [(size_t)MROWS * DD];
__device__ __nv_bfloat16 g_QH [(size_t)MROWS * DHALF];
__device__ __nv_bfloat16 g_QL [(size_t)MROWS * DHALF];
__device__ __nv_bfloat16 g_KH [(size_t)MROWS * DHALF];
__device__ __nv_bfloat16 g_KL [(size_t)MROWS * DHALF];
__device__ __nv_bfloat16 g_KDH[(size_t)MROWS * DHALF];
__device__ __nv_bfloat16 g_KDL[(size_t)MROWS * DHALF];
__device__ __nv_bfloat16 g_VH [(size_t)MROWS * DD];
__device__ __nv_bfloat16 g_VL [(size_t)MROWS * DD];
__device__ __nv_bfloat16 g_AH [(size_t)NCHUNKS * CHUNK * CHUNK];
__device__ __nv_bfloat16 g_AL [(size_t)NCHUNKS * CHUNK * CHUNK];
__device__ __nv_bfloat16 g_SBH[(size_t)NBLOBS * 64 * 128];
__device__ __nv_bfloat16 g_SBL[(size_t)NBLOBS * 64 * 128];

// ================= helpers =================
__device__ __forceinline__ uint32_t smem_u32(const void* p) {
    uint32_t a;
    asm("{ .reg .u64 t; cvta.to.shared.u64 t, %1; cvt.u32.u64 %0, t; }" : "=r"(a) : "l"(p));
    return a;
}
__device__ __forceinline__ void cpasync16(uint32_t dst, const void* src) {
    asm volatile("cp.async.cg.shared.global [%0], [%1], 16;" :: "r"(dst), "l"(src) : "memory");
}
__device__ __forceinline__ void ldsm_x4(uint32_t* r, uint32_t addr) {
    asm volatile("ldmatrix.sync.aligned.m8n8.x4.shared.b16 {%0,%1,%2,%3}, [%4];"
                 : "=r"(r[0]), "=r"(r[1]), "=r"(r[2]), "=r"(r[3]) : "r"(addr));
}
__device__ __forceinline__ void mma16816(float* c, const uint32_t* a, const uint32_t* b) {
    asm volatile(
        "mma.sync.aligned.m16n8k16.row.col.f32.bf16.bf16.f32 "
        "{%0,%1,%2,%3}, {%4,%5,%6,%7}, {%8,%9}, {%0,%1,%2,%3};"
        : "+f"(c[0]), "+f"(c[1]), "+f"(c[2]), "+f"(c[3])
        : "r"(a[0]), "r"(a[1]), "r"(a[2]), "r"(a[3]), "r"(b[0]), "r"(b[1]));
}
__device__ __forceinline__ void mma16816h(float* c, const uint32_t* a, const uint32_t* b) {
    asm volatile(
        "mma.sync.aligned.m16n8k16.row.col.f32.f16.f16.f32 "
        "{%0,%1,%2,%3}, {%4,%5,%6,%7}, {%8,%9}, {%0,%1,%2,%3};"
        : "+f"(c[0]), "+f"(c[1]), "+f"(c[2]), "+f"(c[3])
        : "r"(a[0]), "r"(a[1]), "r"(a[2]), "r"(a[3]), "r"(b[0]), "r"(b[1]));
}
static __device__ __forceinline__ uint32_t sw128(uint32_t o) { return o ^ ((o >> 3) & 0x70); }

// acc[MF][4][4] += A_tile @ B_tile^T over K=128 (2 sw128 K-subtiles) [bf16]
template<int MF>
__device__ __forceinline__ void mma_combo(float (*acc)[4][4], uint32_t Ab, uint32_t abs_,
                                          uint32_t Bb, uint32_t bbs, int mw, int nw, int lane)
{
#pragma unroll
    for (int kb = 0; kb < 2; kb++) {
#pragma unroll
        for (int ks = 0; ks < 4; ks++) {
            uint32_t af[MF][4];
#pragma unroll
            for (int mf = 0; mf < MF; mf++) {
                int row = mw + mf * 16 + (lane & 15);
                uint32_t bo = (uint32_t)(row << 7) + (uint32_t)(ks << 5) + ((lane >> 4) << 4);
                ldsm_x4(af[mf], Ab + kb * abs_ + sw128(bo));
            }
            uint32_t bfr[4][2];
#pragma unroll
            for (int half = 0; half < 2; half++) {
                int i2 = lane >> 3;
                int row = nw + half * 16 + ((i2 >> 1) << 3) + (lane & 7);
                uint32_t bo = (uint32_t)(row << 7) + (uint32_t)(ks << 5) + ((i2 & 1) << 4);
                uint32_t r[4];
                ldsm_x4(r, Bb + kb * bbs + sw128(bo));
                bfr[half * 2][0] = r[0];     bfr[half * 2][1] = r[1];
                bfr[half * 2 + 1][0] = r[2]; bfr[half * 2 + 1][1] = r[3];
            }
#pragma unroll
            for (int mf = 0; mf < MF; mf++)
#pragma unroll
                for (int nf = 0; nf < 4; nf++)
                    mma16816(acc[mf][nf], af[mf], bfr[nf]);
        }
    }
}

// ======================================================================
// gemm2h: fp16 2-pass GEMM (verified R10).
// ======================================================================
__global__ __launch_bounds__(256, 1)
void gemm2h(const __half* __restrict__ AHp,
            const __half* __restrict__ BHp, const __half* __restrict__ BLp,
            float* __restrict__ C, __nv_bfloat16* __restrict__ SHo, __nv_bfloat16* __restrict__ SLo,
            int M, int N, int K, int nsplit, float alpha, const float* __restrict__ bias)
{
    extern __shared__ char smem[];
    const uint32_t sbase = smem_u32(smem);
    const int tid = threadIdx.x;
    const int wid = tid >> 5, lane = tid & 31;
    const int m0 = blockIdx.y * 128, n0 = blockIdx.x * 128;
    const int mw = (wid & 1) * 64, nw = (wid >> 1) * 32;
    const int TOT = K >> 6;

    float acc[4][4][4];
#pragma unroll
    for (int i = 0; i < 4; i++)
#pragma unroll
        for (int j = 0; j < 4; j++)
#pragma unroll
            for (int l = 0; l < 4; l++) acc[i][j][l] = 0.f;

    auto issue = [&](int it) {
        const int k0 = it << 6;
        const uint32_t st = sbase + (uint32_t)(it % 3) * 49152u;
#pragma unroll
        for (int l = 0; l < 4; l++) {
            int c = tid + (l << 8);
            int row = c >> 3;
            uint32_t dst = sw128((uint32_t)(row << 7) + ((c & 7) << 4));
            int el = (c & 7) << 3;
            size_t ao = (size_t)(m0 + row) * K + k0 + el;
            size_t bo = (size_t)(n0 + row) * K + k0 + el;
            cpasync16(st + dst,         AHp + ao);
            cpasync16(st + 16384 + dst, BHp + bo);
            cpasync16(st + 32768 + dst, BLp + bo);
        }
        asm volatile("cp.async.commit_group;" ::: "memory");
    };

    issue(0);
    if (TOT > 1) issue(1);
    for (int it = 0; it < TOT; it++) {
        if (it + 1 < TOT) {
            asm volatile("cp.async.wait_group 1;" ::: "memory");
        } else {
            asm volatile("cp.async.wait_group 0;" ::: "memory");
        }
        __syncthreads();
        const uint32_t st = sbase + (uint32_t)(it % 3) * 49152u;
#pragma unroll
        for (int ks = 0; ks < 4; ks++) {
            uint32_t afH[4][4], bfH[4][2], bfL[4][2];
#pragma unroll
            for (int mf = 0; mf < 4; mf++) {
                int row = mw + mf * 16 + (lane & 15);
                uint32_t bo = (uint32_t)(row << 7) + (uint32_t)(ks << 5) + ((lane >> 4) << 4);
                ldsm_x4(afH[mf], st + sw128(bo));
            }
#pragma unroll
            for (int half = 0; half < 2; half++) {
                int i2 = lane >> 3;
                int row = nw + half * 16 + ((i2 >> 1) << 3) + (lane & 7);
                uint32_t bo = (uint32_t)(row << 7) + (uint32_t)(ks << 5) + ((i2 & 1) << 4);
                uint32_t so = sw128(bo);
                uint32_t r[4];
                ldsm_x4(r, st + 16384 + so);
                bfH[half * 2][0] = r[0];     bfH[half * 2][1] = r[1];
                bfH[half * 2 + 1][0] = r[2]; bfH[half * 2 + 1][1] = r[3];
                ldsm_x4(r, st + 32768 + so);
                bfL[half * 2][0] = r[0];     bfL[half * 2][1] = r[1];
                bfL[half * 2 + 1][0] = r[2]; bfL[half * 2 + 1][1] = r[3];
            }
#pragma unroll
            for (int mf = 0; mf < 4; mf++)
#pragma unroll
                for (int nf = 0; nf < 4; nf++) {
                    mma16816h(acc[mf][nf], afH[mf], bfH[nf]);
                    mma16816h(acc[mf][nf], afH[mf], bfL[nf]);
                }
        }
        if (it + 2 < TOT) issue(it + 2);
    }

    const int rb = m0 + mw + (lane >> 2);
    const int cb = n0 + nw + ((lane & 3) << 1);
    const bool split_region = (n0 < nsplit);
    const int cstride = N - nsplit;
#pragma unroll
    for (int mf = 0; mf < 4; mf++) {
#pragma unroll
        for (int half = 0; half < 2; half++) {
            int row = rb + mf * 16 + half * 8;
#pragma unroll
            for (int nf = 0; nf < 4; nf++) {
                int col = cb + nf * 8;
                float vx = alpha * acc[mf][nf][half * 2 + 0];
                float vy = alpha * acc[mf][nf][half * 2 + 1];
                if (split_region) {
                    __nv_bfloat16 h0 = __float2bfloat16(vx);
                    __nv_bfloat16 h1 = __float2bfloat16(vy);
                    __nv_bfloat16 l0 = __float2bfloat16(vx - __bfloat162float(h0));
                    __nv_bfloat16 l1 = __float2bfloat16(vy - __bfloat162float(h1));
                    *(__nv_bfloat162*)(SHo + (size_t)row * nsplit + col) = __nv_bfloat162(h0, h1);
                    *(__nv_bfloat162*)(SLo + (size_t)row * nsplit + col) = __nv_bfloat162(l0, l1);
                } else {
                    int cc = col - nsplit;
                    if (bias) { vx += bias[cc]; vy += bias[cc + 1]; }
                    float2 v; v.x = vx; v.y = vy;
                    *(float2*)(C + (size_t)row * cstride + cc) = v;
                }
            }
        }
    }
}

// ======================================================================
// akernel (verified): A = qd @ kexp^T, tril, split to bf16.
// ======================================================================
__global__ __launch_bounds__(256, 1)
void akernel(const __nv_bfloat16* __restrict__ QH, const __nv_bfloat16* __restrict__ QL,
             const __nv_bfloat16* __restrict__ KH, const __nv_bfloat16* __restrict__ KL,
             __nv_bfloat16* __restrict__ AH, __nv_bfloat16* __restrict__ AL)
{
    extern __shared__ char smemc[];
    const uint32_t sb = smem_u32(smemc);
    const uint32_t oQH = 0, oQL = 32768, oKH = 65536, oKL = 98304;
    const int tid = threadIdx.x;
    const int wid = tid >> 5, lane = tid & 31;
    const int h = blockIdx.x, ch = blockIdx.y, bb = blockIdx.z;
    const int m0 = bb * TT + ch * CHUNK;
    const int colQ = h * 128;
    const size_t chA = (size_t)((bb * NCH + ch) * HH + h) * 16384;

#pragma unroll
    for (int l = 0; l < 8; l++) {
        int idx = tid + (l << 8);
        int row = idx >> 4, u = idx & 15;
        int kb = u >> 3, sub = u & 7;
        uint32_t dst = (uint32_t)kb * 16384u + sw128((uint32_t)(row << 7) + (sub << 4));
        size_t so = (size_t)(m0 + row) * DHALF + colQ + kb * 64 + sub * 8;
        cpasync16(sb + oQH + dst, QH + so);
        cpasync16(sb + oQL + dst, QL + so);
        cpasync16(sb + oKH + dst, KH + so);
        cpasync16(sb + oKL + dst, KL + so);
    }
    asm volatile("cp.async.commit_group;" ::: "memory");
    asm volatile("cp.async.wait_group 0;" ::: "memory");
    __syncthreads();

    const int mw = (wid & 1) * 64, nw = (wid >> 1) * 32;
    float acc[4][4][4];
#pragma unroll
    for (int i = 0; i < 4; i++)
#pragma unroll
        for (int j = 0; j < 4; j++)
#pragma unroll
            for (int l = 0; l < 4; l++) acc[i][j][l] = 0.f;

    mma_combo<4>(acc, sb + oQH, 16384, sb + oKH, 16384, mw, nw, lane);
    mma_combo<4>(acc, sb + oQH, 16384, sb + oKL, 16384, mw, nw, lane);
    mma_combo<4>(acc, sb + oQL, 16384, sb + oKH, 16384, mw, nw, lane);

#pragma unroll
    for (int mf = 0; mf < 4; mf++) {
#pragma unroll
        for (int half = 0; half < 2; half++) {
            int i = mw + mf * 16 + half * 8 + (lane >> 2);
#pragma unroll
            for (int nf = 0; nf < 4; nf++) {
                int j = nw + nf * 8 + ((lane & 3) << 1);
                float v0 = (j     <= i) ? acc[mf][nf][half * 2 + 0] : 0.f;
                float v1 = (j + 1 <= i) ? acc[mf][nf][half * 2 + 1] : 0.f;
                __nv_bfloat16 h0 = __float2bfloat16(v0);
                __nv_bfloat16 h1 = __float2bfloat16(v1);
                __nv_bfloat16 l0 = __float2bfloat16(v0 - __bfloat162float(h0));
                __nv_bfloat16 l1 = __float2bfloat16(v1 - __bfloat162float(h1));
                size_t oi = chA + (size_t)i * 128 + j;
                *(__nv_bfloat162*)(AH + oi) = __nv_bfloat162(h0, h1);
                *(__nv_bfloat162*)(AL + oi) = __nv_bfloat162(l0, l1);
            }
        }
    }
}

// ======================================================================
// phase1: per (b,h,ch,vsl). o_part = tril(A)@v -> O ; U = kd^T@v -> U blob.
// U blob layout elementwise-matched to S blob byte order.
// ======================================================================
__global__ __launch_bounds__(256, 1)
void phase1_kernel(const __nv_bfloat16* __restrict__ AH, const __nv_bfloat16* __restrict__ AL,
                   const __nv_bfloat16* __restrict__ KDH, const __nv_bfloat16* __restrict__ KDL,
                   const __nv_bfloat16* __restrict__ VH, const __nv_bfloat16* __restrict__ VL,
                   float* __restrict__ O, float* __restrict__ U)
{
    extern __shared__ char smemc[];
    const uint32_t sb = smem_u32(smemc);
    const uint32_t oAH = 0, oAL = 32768, oKT = 65536, oKTl = 98304;
    const uint32_t oVH = 131072, oVL = 147456;   // 160K total

    const int tid = threadIdx.x;
    const int wid = tid >> 5, lane = tid & 31;
    const int ch = blockIdx.x >> 2, vsl = blockIdx.x & 3;
    const int h = blockIdx.y, bb = blockIdx.z;
    const int m0 = bb * TT + ch * CHUNK;
    const int colQ = h * 128;
    const int colV = h * 256 + vsl * 64;
    const size_t chA = (size_t)((bb * NCH + ch) * HH + h) * 16384;
    const size_t ublob = (size_t)(((bb * HH + h) * 4 + vsl) * NCH + ch) * 8192;
    const int mw = (wid & 3) * 32, nw = (wid >> 2) * 32;

    // A tiles via cp.async
#pragma unroll
    for (int l = 0; l < 8; l++) {
        int idx = tid + (l << 8);
        int row = idx >> 4, u = idx & 15;
        int kb = u >> 3, sub = u & 7;
        uint32_t dst = (uint32_t)kb * 16384u + sw128((uint32_t)(row << 7) + (sub << 4));
        size_t sa = chA + (size_t)row * 128 + kb * 64 + sub * 8;
        cpasync16(sb + oAH + dst, AH + sa);
        cpasync16(sb + oAL + dst, AL + sa);
    }
    asm volatile("cp.async.commit_group;" ::: "memory");

    // kdT transpose: [j][d] -> [d][j]
#pragma unroll
    for (int l = 0; l < 32; l++) {
        int idx = tid + (l << 8);
        int j = idx >> 6, d = (idx & 63) << 1;
        uint32_t wv = *(const uint32_t*)(KDH + (size_t)(m0 + j) * DHALF + colQ + d);
        uint32_t wl = *(const uint32_t*)(KDL + (size_t)(m0 + j) * DHALF + colQ + d);
        uint32_t kbo = (uint32_t)(j >> 6) * 16384u;
        uint32_t off0 = kbo + sw128((uint32_t)(d << 7) + ((j & 63) << 1));
        uint32_t off1 = kbo + sw128((uint32_t)((d + 1) << 7) + ((j & 63) << 1));
        *(unsigned short*)(smemc + oKT  + off0) = (unsigned short)(wv & 0xffff);
        *(unsigned short*)(smemc + oKT  + off1) = (unsigned short)(wv >> 16);
        *(unsigned short*)(smemc + oKTl + off0) = (unsigned short)(wl & 0xffff);
        *(unsigned short*)(smemc + oKTl + off1) = (unsigned short)(wl >> 16);
    }
    // vT transpose: [j][n] -> [n][j]
#pragma unroll
    for (int l = 0; l < 16; l++) {
        int idx = tid + (l << 8);
        int j = idx >> 5, n = (idx & 31) << 1;
        uint32_t wv = *(const uint32_t*)(VH + (size_t)(m0 + j) * DD + colV + n);
        uint32_t wl = *(const uint32_t*)(VL + (size_t)(m0 + j) * DD + colV + n);
        uint32_t kbo = (uint32_t)(j >> 6) * 8192u;
        uint32_t off0 = kbo + sw128((uint32_t)(n << 7) + ((j & 63) << 1));
        uint32_t off1 = kbo + sw128((uint32_t)((n + 1) << 7) + ((j & 63) << 1));
        *(unsigned short*)(smemc + oVH + off0) = (unsigned short)(wv & 0xffff);
        *(unsigned short*)(smemc + oVH + off1) = (unsigned short)(wv >> 16);
        *(unsigned short*)(smemc + oVL + off0) = (unsigned short)(wl & 0xffff);
        *(unsigned short*)(smemc + oVL + off1) = (unsigned short)(wl >> 16);
    }
    asm volatile("cp.async.wait_group 0;" ::: "memory");
    __syncthreads();

    // o_part = tril(A)@v
    float acc[2][4][4];
#pragma unroll
    for (int i = 0; i < 2; i++)
#pragma unroll
        for (int j = 0; j < 4; j++)
#pragma unroll
            for (int l = 0; l < 4; l++) acc[i][j][l] = 0.f;
    mma_combo<2>(acc, sb + oAH, 16384, sb + oVH, 8192, mw, nw, lane);
    mma_combo<2>(acc, sb + oAH, 16384, sb + oVL, 8192, mw, nw, lane);
    mma_combo<2>(acc, sb + oAL, 16384, sb + oVH, 8192, mw, nw, lane);
#pragma unroll
    for (int mf = 0; mf < 2; mf++) {
#pragma unroll
        for (int half = 0; half < 2; half++) {
            int row = m0 + mw + mf * 16 + half * 8 + (lane >> 2);
#pragma unroll
            for (int nf = 0; nf < 4; nf++) {
                int col = colV + nw + nf * 8 + ((lane & 3) << 1);
                float2 v;
                v.x = acc[mf][nf][half * 2 + 0];
                v.y = acc[mf][nf][half * 2 + 1];
                *(float2*)&O[(size_t)row * DD + col] = v;
            }
        }
    }

    // U = kd^T @ v
    float uacc[2][4][4];
#pragma unroll
    for (int i = 0; i < 2; i++)
#pragma unroll
        for (int j = 0; j < 4; j++)
#pragma unroll
            for (int l = 0; l < 4; l++) uacc[i][j][l] = 0.f;
    mma_combo<2>(uacc, sb + oKT,  16384, sb + oVH, 8192, mw, nw, lane);
    mma_combo<2>(uacc, sb + oKT,  16384, sb + oVL, 8192, mw, nw, lane);
    mma_combo<2>(uacc, sb + oKTl, 16384, sb + oVH, 8192, mw, nw, lane);
#pragma unroll
    for (int mf = 0; mf < 2; mf++) {
#pragma unroll
        for (int half = 0; half < 2; half++) {
            int d = mw + mf * 16 + half * 8 + (lane >> 2);
            uint32_t kb = (uint32_t)(d >> 6) * 4096u;
            uint32_t d2b = (uint32_t)((d & 63) << 1);
#pragma unroll
            for (int nf = 0; nf < 4; nf++) {
                int n = nw + nf * 8 + ((lane & 3) << 1);
                uint32_t i0 = kb + (sw128(((uint32_t)n << 7) + d2b) >> 1);
                uint32_t i1 = kb + (sw128(((uint32_t)(n + 1) << 7) + d2b) >> 1);
                U[ublob + i0] = uacc[mf][nf][half * 2 + 0];
                U[ublob + i1] = uacc[mf][nf][half * 2 + 1];
            }
        }
    }
}

// ======================================================================
// scan: per (b,h,vsl). S in registers (32/thread). For each chunk:
// write pre-update S blob (bf16 split), then S = dec ⊙ S + U.
// ======================================================================
__global__ __launch_bounds__(256, 1)
void scan_kernel(const float* __restrict__ U, const float* __restrict__ DEC,
                 __nv_bfloat16* __restrict__ SBH, __nv_bfloat16* __restrict__ SBL)
{
    __shared__ float sdec[128];
    const int t = threadIdx.x;
    const int vsl = blockIdx.x, h = blockIdx.y, bb = blockIdx.z;
    const int blobbase = ((bb * HH + h) * 4 + vsl) * NCH;
    const int colQ = h * 128;

    // precompute owned d per group (4 consecutive elems share n, consecutive d)
    int dbase[8];
#pragma unroll
    for (int g = 0; g < 8; g++) {
        uint32_t ibase = (uint32_t)(t + g * 256) * 4;
        uint32_t braw = sw128((ibase & 4095) * 2);
        dbase[g] = (int)(ibase >> 12) * 64 + (int)((braw & 127) >> 1);
    }

    float S[32];
#pragma unroll
    for (int i = 0; i < 32; i++) S[i] = 0.f;

    for (int ch = 0; ch < NCH; ch++) {
        if (t < 128) sdec[t] = DEC[(size_t)(bb * NCH + ch) * DHALF + colQ + t];
        const size_t blob = (size_t)(blobbase + ch) * 8192;
        // write pre-update blob
#pragma unroll
        for (int g = 0; g < 8; g++) {
            uint32_t ibase = (uint32_t)(t + g * 256) * 4;
            float v0 = S[g * 4 + 0], v1 = S[g * 4 + 1], v2 = S[g * 4 + 2], v3 = S[g * 4 + 3];
            __nv_bfloat16 h0 = __float2bfloat16(v0), h1 = __float2bfloat16(v1);
            __nv_bfloat16 h2 = __float2bfloat16(v2), h3 = __float2bfloat16(v3);
            *(__nv_bfloat162*)(SBH + blob + ibase)     = __nv_bfloat162(h0, h1);
            *(__nv_bfloat162*)(SBH + blob + ibase + 2) = __nv_bfloat162(h2, h3);
            __nv_bfloat16 l0 = __float2bfloat16(v0 - __bfloat162float(h0));
            __nv_bfloat16 l1 = __float2bfloat16(v1 - __bfloat162float(h1));
            __nv_bfloat16 l2 = __float2bfloat16(v2 - __bfloat162float(h2));
            __nv_bfloat16 l3 = __float2bfloat16(v3 - __bfloat162float(h3));
            *(__nv_bfloat162*)(SBL + blob + ibase)     = __nv_bfloat162(l0, l1);
            *(__nv_bfloat162*)(SBL + blob + ibase + 2) = __nv_bfloat162(l2, l3);
        }
        __syncthreads();   // sdec ready
        // update S
#pragma unroll
        for (int g = 0; g < 8; g++) {
            uint32_t ibase = (uint32_t)(t + g * 256) * 4;
            float4 u = *(const float4*)(U + blob + ibase);
            int d0 = dbase[g];
            S[g * 4 + 0] = sdec[d0 + 0] * S[g * 4 + 0] + u.x;
            S[g * 4 + 1] = sdec[d0 + 1] * S[g * 4 + 1] + u.y;
            S[g * 4 + 2] = sdec[d0 + 2] * S[g * 4 + 2] + u.z;
            S[g * 4 + 3] = sdec[d0 + 3] * S[g * 4 + 3] + u.w;
        }
        __syncthreads();   // reads done before next chunk's sdec overwrite
    }
}

// ======================================================================
// o2: per (b,h,ch,vsl). O += qd @ S_ch  (no transposes)
// ======================================================================
__global__ __launch_bounds__(256, 1)
void o2_kernel(const __nv_bfloat16* __restrict__ QH, const __nv_bfloat16* __restrict__ QL,
               const __nv_bfloat16* __restrict__ SBH, const __nv_bfloat16* __restrict__ SBL,
               float* __restrict__ O)
{
    extern __shared__ char smemc[];
    const uint32_t sb = smem_u32(smemc);
    const uint32_t oQH = 0, oQL = 32768, oSH = 65536, oSL = 81920;   // 96K

    const int tid = threadIdx.x;
    const int wid = tid >> 5, lane = tid & 31;
    const int ch = blockIdx.x >> 2, vsl = blockIdx.x & 3;
    const int h = blockIdx.y, bb = blockIdx.z;
    const int m0 = bb * TT + ch * CHUNK;
    const int colQ = h * 128;
    const int colV = h * 256 + vsl * 64;
    const size_t blob = (size_t)(((bb * HH + h) * 4 + vsl) * NCH + ch) * 8192;
    const int mw = (wid & 3) * 32, nw = (wid >> 2) * 32;

#pragma unroll
    for (int l = 0; l < 8; l++) {
        int idx = tid + (l << 8);
        int row = idx >> 4, u = idx & 15;
        int kb = u >> 3, sub = u & 7;
        uint32_t dst = (uint32_t)kb * 16384u + sw128((uint32_t)(row << 7) + (sub << 4));
        size_t so = (size_t)(m0 + row) * DHALF + colQ + kb * 64 + sub * 8;
        cpasync16(sb + oQH + dst, QH + so);
        cpasync16(sb + oQL + dst, QL + so);
    }
#pragma unroll
    for (int l = 0; l < 4; l++) {
        int i = tid + (l << 8);
        cpasync16(sb + oSH + (i << 4), SBH + blob + (size_t)i * 8);
        cpasync16(sb + oSL + (i << 4), SBL + blob + (size_t)i * 8);
    }
    asm volatile("cp.async.commit_group;" ::: "memory");
    asm volatile("cp.async.wait_group 0;" ::: "memory");
    __syncthreads();

    float acc[2][4][4];
#pragma unroll
    for (int i = 0; i < 2; i++)
#pragma unroll
        for (int j = 0; j < 4; j++)
#pragma unroll
            for (int l = 0; l < 4; l++) acc[i][j][l] = 0.f;

    mma_combo<2>(acc, sb + oQH, 16384, sb + oSH, 8192, mw, nw, lane);
    mma_combo<2>(acc, sb + oQH, 16384, sb + oSL, 8192, mw, nw, lane);
    mma_combo<2>(acc, sb + oQL, 16384, sb + oSH, 8192, mw, nw, lane);

#pragma unroll
    for (int mf = 0; mf < 2; mf++) {
#pragma unroll
        for (int half = 0; half < 2; half++) {
            int row = m0 + mw + mf * 16 + half * 8 + (lane >> 2);
#pragma unroll
            for (int nf = 0; nf < 4; nf++) {
                int col = colV + nw + nf * 8 + ((lane & 3) << 1);
                float2 v = *(float2*)&O[(size_t)row * DD + col];
                v.x += acc[mf][nf][half * 2 + 0];
                v.y += acc[mf][nf][half * 2 + 1];
                *(float2*)&O[(size_t)row * DD + col] = v;
            }
        }
    }
}

// ======================================================================
// x -> fp16
// ======================================================================
__global__ void xhalf(const float4* __restrict__ X, __half* __restrict__ H, int n4)
{
    int i = blockIdx.x * blockDim.x + threadIdx.x;
    if (i >= n4) return;
    float4 v = X[i];
    __half2* Hp = (__half2*)H;
    Hp[i * 2]     = __floats2half2_rn(v.x, v.y);
    Hp[i * 2 + 1] = __floats2half2_rn(v.z, v.w);
}

// ======================================================================
// transpose W [K,N] -> combined WT fp16 hi/lo rows [rowoff..), x alpha
// ======================================================================
__global__ void wsplit_t(const float* __restrict__ W, __half* __restrict__ Th,
                         __half* __restrict__ Tl, int K, int N, int rowoff, float alpha)
{
    __shared__ float t[32][33];
    const int n0 = blockIdx.x * 32, k0 = blockIdx.y * 32;
    const int tx = threadIdx.x, ty = threadIdx.y;
#pragma unroll
    for (int i = 0; i < 4; i++) {
        int k = ty + i * 8;
        t[k][tx] = W[(size_t)(k0 + k) * N + n0 + tx];
    }
    __syncthreads();
#pragma unroll
    for (int i = 0; i < 4; i++) {
        int n = ty + i * 8;
        float v = t[tx][n] * alpha;
        __half h = __float2half(v);
        size_t oi = (size_t)(rowoff + n0 + n) * K + k0 + tx;
        Th[oi] = h;
        Tl[oi] = __float2half(v - __half2float(h));
    }
}

// ======================================================================
// kg1: out[M,16] = x @ Wkg1. warp per row.
// ======================================================================
__global__ void kg1_kernel(const float* __restrict__ x, const float* __restrict__ W1,
                           float* __restrict__ out)
{
    const int wid = threadIdx.x >> 5, lane = threadIdx.x & 31;
    const int row = blockIdx.x * 8 + wid;
    const float* xp = x + (size_t)row * DD;
    float acc[16];
#pragma unroll
    for (int c = 0; c < 16; c++) acc[c] = 0.f;
    for (int k = lane; k < DD; k += 32) {
        float xv = xp[k];
        const float4* wp = (const float4*)(W1 + (size_t)k * 16);
        float4 w0 = wp[0], w1 = wp[1], w2 = wp[2], w3 = wp[3];
        acc[0]  += xv * w0.x; acc[1]  += xv * w0.y; acc[2]  += xv * w0.z; acc[3]  += xv * w0.w;
        acc[4]  += xv * w1.x; acc[5]  += xv * w1.y; acc[6]  += xv * w1.z; acc[7]  += xv * w1.w;
        acc[8]  += xv * w2.x; acc[9]  += xv * w2.y; acc[10] += xv * w2.z; acc[11] += xv * w2.w;
        acc[12] += xv * w3.x; acc[13] += xv * w3.y; acc[14] += xv * w3.z; acc[15] += xv * w3.w;
    }
#pragma unroll
    for (int c = 0; c < 16; c++) {
        float v = acc[c];
#pragma unroll
        for (int off = 16; off; off >>= 1) v += __shfl_xor_sync(0xFFFFFFFFu, v, off);
        if (lane == 0) out[(size_t)row * 16 + c] = v;
    }
}

// ======================================================================
// gk = log_sigmoid(KG1 @ Wkg2 + bkg2) / 16
// ======================================================================
__global__ void gk_kernel(const float* __restrict__ KG1,
                          const float* __restrict__ W2,
                          const float* __restrict__ b2,
                          float* __restrict__ GK)
{
    __shared__ float a[16];
    int m = blockIdx.x;
    if (threadIdx.x < 16) a[threadIdx.x] = KG1[(size_t)m * 16 + threadIdx.x];
    __syncthreads();
    for (int c = threadIdx.x; c < DHALF; c += 128) {
        float z = b2[c];
#pragma unroll
        for (int r = 0; r < 16; r++) z = fmaf(a[r], W2[(size_t)r * DHALF + c], z);
        float e = __expf(-fabsf(z));
        float l = __logf(1.f + e);
        float ls = (z >= 0.f) ? -l : (z - l);
        GK[(size_t)m * DHALF + c] = ls * INV_NORM_GK;
    }
}

// ======================================================================
// decay precompute
// ======================================================================
__global__ void prep_kernel(const float* __restrict__ QK,
                            const float* __restrict__ GK,
                            __nv_bfloat16* __restrict__ QHo, __nv_bfloat16* __restrict__ QLo,
                            __nv_bfloat16* __restrict__ KHo, __nv_bfloat16* __restrict__ KLo,
                            __nv_bfloat16* __restrict__ KDHo, __nv_bfloat16* __restrict__ KDLo,
                            float* __restrict__ DEC)
{
    int g = blockIdx.x * blockDim.x + threadIdx.x;
    int col = g & (DHALF - 1);
    int bc  = g >> 10;
    int row0 = ((bc >> 4) * TT) + ((bc & 15) * CHUNK);
    size_t baseg = (size_t)row0 * DHALF + col;
    size_t baseq = (size_t)row0 * 2048 + col;

    float gs = 0.f;
#pragma unroll 4
    for (int i = 0; i < CHUNK; i++) gs += GK[baseg + (size_t)i * DHALF];
    float egs = __expf(gs);

    float gc = 0.f;
    for (int i = 0; i < CHUNK; i++) {
        size_t idx = baseg + (size_t)i * DHALF;
        size_t qdx = baseq + (size_t)i * 2048;
        gc += GK[idx];
        float eg = __expf(gc);
        float qd = QK[qdx] * eg;
        float kv = QK[qdx + 1024];
        float ke = __fdividef(kv, eg);
        float kd = ke * egs;
        __nv_bfloat16 qh = __float2bfloat16(qd);
        __nv_bfloat16 kh = __float2bfloat16(ke);
        __nv_bfloat16 dh = __float2bfloat16(kd);
        QHo[idx]  = qh; QLo[idx]  = __float2bfloat16(qd - __bfloat162float(qh));
        KHo[idx]  = kh; KLo[idx]  = __float2bfloat16(ke - __bfloat162float(kh));
        KDHo[idx] = dh; KDLo[idx] = __float2bfloat16(kd - __bfloat162float(dh));
    }
    DEC[(size_t)bc * DHALF + col] = egs;
}

// ======================================================================
// GroupNorm(256) * silu(g) -> fp16
// ======================================================================
__global__ void norm_gate_kernel(const float* __restrict__ O,
                                 const float* __restrict__ G,
                                 __half* __restrict__ PH)
{
    int m = blockIdx.x, h = blockIdx.y;
    int tid = threadIdx.x;
    size_t idx = (size_t)m * DD + h * DV + tid;
    float v = O[idx];
    float s = v, s2 = v * v;
#pragma unroll
    for (int off = 16; off; off >>= 1) {
        s  += __shfl_xor_sync(0xFFFFFFFFu, s,  off);
        s2 += __shfl_xor_sync(0xFFFFFFFFu, s2, off);
    }
    __shared__ float ws[8], ws2[8];
    int w = tid >> 5, l = tid & 31;
    if (l == 0) { ws[w] = s; ws2[w] = s2; }
    __syncthreads();
    float ts = 0.f, ts2 = 0.f;
#pragma unroll
    for (int i = 0; i < 8; i++) { ts += ws[i]; ts2 += ws2[i]; }
    float mu = ts * (1.f / 256.f);
    float var = ts2 * (1.f / 256.f) - mu * mu;
    float nv = (v - mu) * rsqrtf(var + 1e-5f);
    float gt = G[idx];
    float sg = gt / (1.f + __expf(-gt));
    PH[idx] = __float2half(sg * nv);
}

// ======================================================================
extern "C" void kernel_launch(void* const* d_in, const int* in_sizes, int n_in,
                              void* d_out, int out_size)
{
    const float* x    = (const float*)d_in[0];
    const float* Wq   = (const float*)d_in[1];
    const float* Wk   = (const float*)d_in[2];
    const float* Wkg1 = (const float*)d_in[3];
    const float* Wkg2 = (const float*)d_in[4];
    const float* bkg2 = (const float*)d_in[5];
    const float* Wv   = (const float*)d_in[6];
    const float* Wg   = (const float*)d_in[7];
    const float* bg   = (const float*)d_in[8];
    const float* Wo   = (const float*)d_in[9];
    float* out = (float*)d_out;

    float *pQK, *pGK, *pKG1, *pDEC, *pG, *pO, *pU;
    __half *pXH, *pWTH, *pWTL, *pPH;
    __nv_bfloat16 *pQH, *pQL, *pKH, *pKL, *pKDH, *pKDL, *pVH, *pVL, *pAH, *pAL, *pSBH, *pSBL;
    cudaGetSymbolAddress((void**)&pQK,  g_QK);
    cudaGetSymbolAddress((void**)&pGK,  g_GK);
    cudaGetSymbolAddress((void**)&pKG1, g_KG1);
    cudaGetSymbolAddress((void**)&pDEC, g_DEC);
    cudaGetSymbolAddress((void**)&pG,   g_G);
    cudaGetSymbolAddress((void**)&pO,   g_O);
    cudaGetSymbolAddress((void**)&pU,   g_U);
    cudaGetSymbolAddress((void**)&pXH,  g_XH);
    cudaGetSymbolAddress((void**)&pWTH, g_WTH);
    cudaGetSymbolAddress((void**)&pWTL, g_WTL);
    cudaGetSymbolAddress((void**)&pPH,  g_PH);
    cudaGetSymbolAddress((void**)&pQH,  g_QH);
    cudaGetSymbolAddress((void**)&pQL,  g_QL);
    cudaGetSymbolAddress((void**)&pKH,  g_KH);
    cudaGetSymbolAddress((void**)&pKL,  g_KL);
    cudaGetSymbolAddress((void**)&pKDH, g_KDH);
    cudaGetSymbolAddress((void**)&pKDL, g_KDL);
    cudaGetSymbolAddress((void**)&pVH,  g_VH);
    cudaGetSymbolAddress((void**)&pVL,  g_VL);
    cudaGetSymbolAddress((void**)&pAH,  g_AH);
    cudaGetSymbolAddress((void**)&pAL,  g_AL);
    cudaGetSymbolAddress((void**)&pSBH, g_SBH);
    cudaGetSymbolAddress((void**)&pSBL, g_SBL);

    cudaFuncSetAttribute(gemm2h,        cudaFuncAttributeMaxDynamicSharedMemorySize, 147456);
    cudaFuncSetAttribute(akernel,       cudaFuncAttributeMaxDynamicSharedMemorySize, 131072);
    cudaFuncSetAttribute(phase1_kernel, cudaFuncAttributeMaxDynamicSharedMemorySize, 163840);
    cudaFuncSetAttribute(o2_kernel,     cudaFuncAttributeMaxDynamicSharedMemorySize, 98304);

    dim3 tb(32, 8);
    int n4 = MROWS * DD / 4;

    // x -> fp16 ; weights -> combined WT fp16 hi/lo (Q|K*scale|V|G|O)
    xhalf<<<(n4 + 255) / 256, 256>>>((const float4*)x, pXH, n4);
    kg1_kernel<<<MROWS / 8, 256>>>(x, Wkg1, pKG1);
    wsplit_t<<<dim3(DHALF / 32, DD / 32), tb>>>(Wq, pWTH, pWTL, DD, DHALF, 0, 1.0f);
    wsplit_t<<<dim3(DHALF / 32, DD / 32), tb>>>(Wk, pWTH, pWTL, DD, DHALF, 1024, SCALING);
    wsplit_t<<<dim3(DD / 32, DD / 32), tb>>>(Wv, pWTH, pWTL, DD, DD, 2048, 1.0f);
    wsplit_t<<<dim3(DD / 32, DD / 32), tb>>>(Wg, pWTH, pWTL, DD, DD, 4096, 1.0f);
    wsplit_t<<<dim3(DD / 32, DD / 32), tb>>>(Wo, pWTH, pWTL, DD, DD, 6144, 1.0f);

    // fused Q+K projection (N=2048, fp32 out)
    gemm2h<<<dim3(2048 / 128, MROWS / 128), 256, 147456>>>(pXH, pWTH, pWTL,
        pQK, nullptr, nullptr, MROWS, 2048, DD, 0, 1.0f, nullptr);

    // gk + decay precompute
    gk_kernel<<<MROWS, 128>>>(pKG1, Wkg2, bkg2, pGK);
    prep_kernel<<<256, 256>>>(pQK, pGK, pQH, pQL, pKH, pKL, pKDH, pKDL, pDEC);

    // A chunks
    akernel<<<dim3(HH, NCH, BB), 256, 131072>>>(pQH, pQL, pKH, pKL, pAH, pAL);

    // fused V+G projection (N=4096; V bf16 split, G fp32+bias)
    gemm2h<<<dim3(4096 / 128, MROWS / 128), 256, 147456>>>(pXH,
        pWTH + (size_t)2048 * DD, pWTL + (size_t)2048 * DD,
        pG, pVH, pVL, MROWS, 4096, DD, 2048, 1.0f, bg);

    // parallel: O_intra + U chunks
    phase1_kernel<<<dim3(NCH * 4, HH, BB), 256, 163840>>>(pAH, pAL, pKDH, pKDL,
                                                          pVH, pVL, pO, pU);
    // fast elementwise scan -> S blobs
    scan_kernel<<<dim3(4, HH, BB), 256>>>(pU, pDEC, pSBH, pSBL);
    // parallel: O += qd @ S
    o2_kernel<<<dim3(NCH * 4, HH, BB), 256, 98304>>>(pQH, pQL, pSBH, pSBL, pO);

    // groupnorm + silu gate -> fp16
    norm_gate_kernel<<<dim3(MROWS, HH), 256>>>(pO, pG, pPH);

    // output projection (fp32 out)
    gemm2h<<<dim3(DD / 128, MROWS / 128), 256, 147456>>>(pPH,
        pWTH + (size_t)6144 * DD, pWTL + (size_t)6144 * DD,
        out, nullptr, nullptr, MROWS, DD, DD, 0, 1.0f, nullptr);
}